// round 3
// baseline (speedup 1.0000x reference)
#include <cuda_runtime.h>
#include <math.h>

// Problem dims
#define B_  256
#define T_  128
#define I_  256
#define H_  512
#define G4  2048   // 4*H
#define K0  768    // I + H   (layer0 concatenated K)
#define K1  1024   // H + H   (layer1 concatenated K)

// GEMM tile
#define BM 64
#define BN 64
#define BK 16

// ---------------- scratch (allocation-free: __device__ globals) ----------------
__device__ float g_W0p[G4 * K0];   // 6 MB  permuted [W_ih0 | W_hh0], gate-interleaved rows
__device__ float g_W1p[G4 * K1];   // 8 MB  permuted [W_ih1 | W_hh1]
__device__ float g_b0p[G4];
__device__ float g_b1p[G4];
__device__ float g_h0[2][B_ * H_]; // ping-pong hidden states
__device__ float g_h1[2][B_ * H_];
__device__ float g_c0[B_ * H_];
__device__ float g_c1[B_ * H_];

// ---------------- prologue: permute weights so col p = 4*j + q <- orig row q*H + j
__global__ void permute_kernel(const float* __restrict__ Wih0, const float* __restrict__ Whh0,
                               const float* __restrict__ bih0, const float* __restrict__ bhh0,
                               const float* __restrict__ Wih1, const float* __restrict__ Whh1,
                               const float* __restrict__ bih1, const float* __restrict__ bhh1)
{
    int stride = gridDim.x * blockDim.x;
    int tid0 = blockIdx.x * blockDim.x + threadIdx.x;

    for (int idx = tid0; idx < G4 * K0; idx += stride) {
        int p = idx / K0, k = idx - p * K0;
        int j = p >> 2, q = p & 3;
        int norig = q * H_ + j;
        g_W0p[idx] = (k < I_) ? Wih0[norig * I_ + k] : Whh0[norig * H_ + (k - I_)];
    }
    for (int idx = tid0; idx < G4 * K1; idx += stride) {
        int p = idx / K1, k = idx - p * K1;
        int j = p >> 2, q = p & 3;
        int norig = q * H_ + j;
        g_W1p[idx] = (k < H_) ? Wih1[norig * H_ + k] : Whh1[norig * H_ + (k - H_)];
    }
    for (int p = tid0; p < G4; p += stride) {
        int j = p >> 2, q = p & 3;
        int norig = q * H_ + j;
        g_b0p[p] = bih0[norig] + bhh0[norig];
        g_b1p[p] = bih1[norig] + bhh1[norig];
    }
}

// ---------------- init: load h, c (shape (B, 2, H)) into state buffers (ping index 0)
__global__ void init_state_kernel(const float* __restrict__ h, const float* __restrict__ c)
{
    int stride = gridDim.x * blockDim.x;
    for (int idx = blockIdx.x * blockDim.x + threadIdx.x; idx < B_ * H_; idx += stride) {
        int b = idx / H_, j = idx - b * H_;
        g_h0[0][idx] = h[b * 2 * H_ + j];
        g_h1[0][idx] = h[b * 2 * H_ + H_ + j];
        g_c0[idx]    = c[b * 2 * H_ + j];
        g_c1[idx]    = c[b * 2 * H_ + H_ + j];
    }
}

// ---------------- fused GEMM + LSTM cell, one kernel per (step, layer)
// gates[b, 4j+q] = sum_k A[b,k] * Wp[4j+q, k]  (+ bias in epilogue)
// LAYER 0: A = [x_t (I) | mask*h0_prev (H)],  K = 768
// LAYER 1: A = [h0_new (H) | mask*h1_prev (H)], K = 1024
template<int LAYER>
__global__ void __launch_bounds__(256) lstm_step_kernel(
    const float* __restrict__ input,
    const int* __restrict__ is_init,    // jax bool -> int32 in harness
    float* __restrict__ out,
    int t)
{
    constexpr int K = (LAYER == 0) ? K0 : K1;
    const float* Wp = (LAYER == 0) ? g_W0p : g_W1p;
    const float* bp = (LAYER == 0) ? g_b0p : g_b1p;
    int ping = t & 1;
    const float* hprev = (LAYER == 0) ? g_h0[ping] : g_h1[ping];
    const float* h0new = g_h0[ping ^ 1];                      // layer1's fresh input
    float* hnext = (LAYER == 0) ? g_h0[ping ^ 1] : g_h1[ping ^ 1];
    float* cbuf  = (LAYER == 0) ? g_c0 : g_c1;

    __shared__ float As[BK][BM];
    __shared__ float Bs[BK][BN];

    const int bn = blockIdx.x;          // 0..31 (gate-col tile)
    const int bm = blockIdx.y;          // 0..3  (batch tile)
    const int tid = threadIdx.x;
    const int tx = tid & 15, ty = tid >> 4;

    float acc[4][4] = {};

    // loader: each thread loads one float4 along k for A and for B
    const int lrow = tid >> 2;          // 0..63
    const int lk4  = (tid & 3) * 4;     // 0,4,8,12

    const int gb = bm * BM + lrow;      // batch row this thread loads for A
    const float hmask = is_init[gb * T_ + t] ? 0.0f : 1.0f;

    const float* xrow = input + (size_t)gb * T_ * I_ + (size_t)t * I_;
    const float* Arow_h = hprev + gb * H_;
    const float* Arow_h0 = h0new + gb * H_;
    const float* Wrow = Wp + (size_t)(bn * BN + lrow) * K + lk4;

    for (int k0 = 0; k0 < K; k0 += BK) {
        int k = k0 + lk4;
        float4 av, bv;
        if (LAYER == 0) {
            if (k < I_) {
                av = *(const float4*)(xrow + k);
            } else {
                av = *(const float4*)(Arow_h + (k - I_));
                av.x *= hmask; av.y *= hmask; av.z *= hmask; av.w *= hmask;
            }
        } else {
            if (k < H_) {
                av = *(const float4*)(Arow_h0 + k);
            } else {
                av = *(const float4*)(Arow_h + (k - H_));
                av.x *= hmask; av.y *= hmask; av.z *= hmask; av.w *= hmask;
            }
        }
        bv = *(const float4*)(Wrow);
        Wrow += BK;

        __syncthreads();  // previous iteration's smem reads done
        As[lk4 + 0][lrow] = av.x; As[lk4 + 1][lrow] = av.y;
        As[lk4 + 2][lrow] = av.z; As[lk4 + 3][lrow] = av.w;
        Bs[lk4 + 0][lrow] = bv.x; Bs[lk4 + 1][lrow] = bv.y;
        Bs[lk4 + 2][lrow] = bv.z; Bs[lk4 + 3][lrow] = bv.w;
        __syncthreads();

        #pragma unroll
        for (int kk = 0; kk < BK; kk++) {
            float4 a4 = *(const float4*)&As[kk][ty * 4];
            float4 b4 = *(const float4*)&Bs[kk][tx * 4];
            float ar[4] = {a4.x, a4.y, a4.z, a4.w};
            float br[4] = {b4.x, b4.y, b4.z, b4.w};
            #pragma unroll
            for (int r = 0; r < 4; r++)
                #pragma unroll
                for (int c = 0; c < 4; c++)
                    acc[r][c] += ar[r] * br[c];
        }
    }

    // Epilogue: this thread's 4 cols are (i,f,g,o) of hidden unit j
    const int j  = bn * 16 + tx;
    const int p0 = bn * BN + tx * 4;
    const float bi = bp[p0 + 0], bf = bp[p0 + 1], bg = bp[p0 + 2], bo = bp[p0 + 3];

    #pragma unroll
    for (int r = 0; r < 4; r++) {
        const int b = bm * BM + ty * 4 + r;
        float ig = acc[r][0] + bi;
        float fg = acc[r][1] + bf;
        float gg = acc[r][2] + bg;
        float og = acc[r][3] + bo;
        float si = 1.0f / (1.0f + expf(-ig));
        float sf = 1.0f / (1.0f + expf(-fg));
        float so = 1.0f / (1.0f + expf(-og));
        float tg = tanhf(gg);
        float cold = is_init[b * T_ + t] ? 0.0f : cbuf[b * H_ + j];
        float cn = sf * cold + si * tg;
        float hn = so * tanhf(cn);
        cbuf[b * H_ + j]  = cn;
        hnext[b * H_ + j] = hn;
        if (LAYER == 1)
            out[(size_t)b * T_ * H_ + (size_t)t * H_ + j] = hn;
    }
}

// ---------------- epilogue: pack h_n (B,2,H) and c_n (B,2,H) after output (B,T,H)
__global__ void finalize_kernel(float* __restrict__ out)
{
    const size_t off1 = (size_t)B_ * T_ * H_;
    const size_t off2 = off1 + (size_t)B_ * 2 * H_;
    int stride = gridDim.x * blockDim.x;
    for (int idx = blockIdx.x * blockDim.x + threadIdx.x; idx < B_ * H_; idx += stride) {
        int b = idx / H_, j = idx - b * H_;
        // T=128 even -> final states live in ping index 0
        out[off1 + (size_t)b * 2 * H_ + j]       = g_h0[0][idx];
        out[off1 + (size_t)b * 2 * H_ + H_ + j]  = g_h1[0][idx];
        out[off2 + (size_t)b * 2 * H_ + j]       = g_c0[idx];
        out[off2 + (size_t)b * 2 * H_ + H_ + j]  = g_c1[idx];
    }
}

extern "C" void kernel_launch(void* const* d_in, const int* in_sizes, int n_in,
                              void* d_out, int out_size)
{
    const float* input   = (const float*)d_in[0];
    const int*   is_init = (const int*)d_in[1];   // bool -> int32
    const float* h       = (const float*)d_in[2];
    const float* c       = (const float*)d_in[3];
    const float* Wih0    = (const float*)d_in[4];
    const float* Whh0    = (const float*)d_in[5];
    const float* bih0    = (const float*)d_in[6];
    const float* bhh0    = (const float*)d_in[7];
    const float* Wih1    = (const float*)d_in[8];
    const float* Whh1    = (const float*)d_in[9];
    const float* bih1    = (const float*)d_in[10];
    const float* bhh1    = (const float*)d_in[11];
    float* out = (float*)d_out;

    permute_kernel<<<296, 256>>>(Wih0, Whh0, bih0, bhh0, Wih1, Whh1, bih1, bhh1);
    init_state_kernel<<<148, 256>>>(h, c);

    dim3 grid(G4 / BN, B_ / BM);  // (32, 4) = 128 blocks
    for (int t = 0; t < T_; t++) {
        lstm_step_kernel<0><<<grid, 256>>>(input, is_init, out, t);
        lstm_step_kernel<1><<<grid, 256>>>(input, is_init, out, t);
    }

    finalize_kernel<<<148, 256>>>(out);
}

// round 4
// speedup vs baseline: 1.7643x; 1.7643x over previous
#include <cuda_runtime.h>
#include <math.h>
#include <stdint.h>

// Problem dims
#define B_  256
#define T_  128
#define I_  256
#define H_  512
#define G4  2048   // 4*H
#define K0  768    // I + H
#define K1  1024   // H + H

// GEMM tile
#define BM  64
#define BN  64
#define BKK 32     // k per smem stage
#define SP  72     // smem row stride (72 % 32 == 8 -> conflict-free frag loads)

// ---------------- scratch ----------------
// Weights in k-sliced layout: [kg = k/8][p (permuted col)][ki = k%8], tf32-rounded
__device__ float g_W0p[(K0/8) * G4 * 8];   // 6 MB
__device__ float g_W1p[(K1/8) * G4 * 8];   // 8 MB
__device__ float g_b0p[G4];
__device__ float g_b1p[G4];
__device__ float g_h0[2][B_ * H_];
__device__ float g_h1[2][B_ * H_];
__device__ float g_c0[B_ * H_];
__device__ float g_c1[B_ * H_];

// column permutation: p -> original gate row q*H + j
// group g = p>>4 holds units j = 4g..4g+3; within group:
//   pp in [0,8):  gate = pp&1 (i/f), unit = pp>>1
//   pp in [8,16): gate = 2+(pp&1) (g/o), unit = (pp-8)>>1
__device__ __forceinline__ int p2norig(int p) {
    int g = p >> 4, pp = p & 15;
    int q = (pp < 8) ? (pp & 1) : (2 + (pp & 1));
    int u = (pp < 8) ? (pp >> 1) : ((pp - 8) >> 1);
    return q * H_ + g * 4 + u;
}

__device__ __forceinline__ uint32_t tf32_bits(float x) {
    uint32_t u;
    asm("cvt.rna.tf32.f32 %0, %1;" : "=r"(u) : "f"(x));
    return u;
}

// ---------------- prologue: permute + tf32-round + k-slice weights ----------------
__global__ void permute_kernel(const float* __restrict__ Wih0, const float* __restrict__ Whh0,
                               const float* __restrict__ bih0, const float* __restrict__ bhh0,
                               const float* __restrict__ Wih1, const float* __restrict__ Whh1,
                               const float* __restrict__ bih1, const float* __restrict__ bhh1)
{
    int stride = gridDim.x * blockDim.x;
    int tid0 = blockIdx.x * blockDim.x + threadIdx.x;

    for (int idx = tid0; idx < (K0/8) * G4 * 8; idx += stride) {
        int ki = idx & 7;
        int rest = idx >> 3;
        int p = rest & (G4 - 1);
        int kg = rest >> 11;            // rest / G4
        int k = kg * 8 + ki;
        int norig = p2norig(p);
        float v = (k < I_) ? Wih0[norig * I_ + k] : Whh0[norig * H_ + (k - I_)];
        g_W0p[idx] = __uint_as_float(tf32_bits(v));
    }
    for (int idx = tid0; idx < (K1/8) * G4 * 8; idx += stride) {
        int ki = idx & 7;
        int rest = idx >> 3;
        int p = rest & (G4 - 1);
        int kg = rest >> 11;
        int k = kg * 8 + ki;
        int norig = p2norig(p);
        float v = (k < H_) ? Wih1[norig * H_ + k] : Whh1[norig * H_ + (k - H_)];
        g_W1p[idx] = __uint_as_float(tf32_bits(v));
    }
    for (int p = tid0; p < G4; p += stride) {
        int norig = p2norig(p);
        g_b0p[p] = bih0[norig] + bhh0[norig];
        g_b1p[p] = bih1[norig] + bhh1[norig];
    }
}

__global__ void init_state_kernel(const float* __restrict__ h, const float* __restrict__ c)
{
    int stride = gridDim.x * blockDim.x;
    for (int idx = blockIdx.x * blockDim.x + threadIdx.x; idx < B_ * H_; idx += stride) {
        int b = idx / H_, j = idx - b * H_;
        g_h0[0][idx] = h[b * 2 * H_ + j];
        g_h1[0][idx] = h[b * 2 * H_ + H_ + j];
        g_c0[idx]    = c[b * 2 * H_ + j];
        g_c1[idx]    = c[b * 2 * H_ + H_ + j];
    }
}

// ---------------- fused tf32 mma.sync GEMM + LSTM cell ----------------
// gates[b, p] = sum_k A[b,k] * Wp[p, k]; column permutation puts (i,f,g,o) of one
// unit into one thread's mma C fragments.
template<int LAYER>
__global__ void __launch_bounds__(256) lstm_step_kernel(
    const float* __restrict__ input,
    const int* __restrict__ is_init,
    float* __restrict__ out,
    int t)
{
    constexpr int K = (LAYER == 0) ? K0 : K1;
    const float* Wp = (LAYER == 0) ? g_W0p : g_W1p;
    const float* bp = (LAYER == 0) ? g_b0p : g_b1p;
    const int ping = t & 1;
    const float* hprev = (LAYER == 0) ? g_h0[ping] : g_h1[ping];
    const float* h0new = g_h0[ping ^ 1];
    float* hnext = (LAYER == 0) ? g_h0[ping ^ 1] : g_h1[ping ^ 1];
    float* cbuf  = (LAYER == 0) ? g_c0 : g_c1;

    __shared__ uint32_t As[BKK][SP];   // [k][m]
    __shared__ uint32_t Bs[BKK][SP];   // [k][n]

    const int tid = threadIdx.x;
    const int bn = blockIdx.x;         // 0..31  (64 cols of permuted gates)
    const int bm = blockIdx.y;         // 0..3   (64 batch rows)
    const int wid = tid >> 5, lane = tid & 31;
    const int wm = wid >> 2;           // 0..1  warp row (32 m each)
    const int wn = wid & 3;            // 0..3  warp col (16 n each)
    const int gi = lane >> 2;          // groupID   (0..7)
    const int tg = lane & 3;           // threadID_in_group (0..3)

    // loader mapping: thread = (row lm, k-slice ks of 8)
    const int lm = tid & 63;
    const int ks = tid >> 6;

    const int gb_l = bm * BM + lm;
    const float hmask = is_init[gb_l * T_ + t] ? 0.0f : 1.0f;
    const float* xrow  = input + (size_t)gb_l * T_ * I_ + (size_t)t * I_;
    const float* hrow  = hprev + gb_l * H_;
    const float* h0row = h0new + gb_l * H_;

    float4 aR[2], bR[2];

    auto loadA = [&](int k0) {
        #pragma unroll
        for (int h = 0; h < 2; h++) {
            int kk = k0 + ks * 8 + h * 4;
            float4 v;
            if (LAYER == 0) {
                if (kk < I_) v = *(const float4*)(xrow + kk);
                else {
                    v = *(const float4*)(hrow + (kk - I_));
                    v.x *= hmask; v.y *= hmask; v.z *= hmask; v.w *= hmask;
                }
            } else {
                if (kk < H_) v = *(const float4*)(h0row + kk);
                else {
                    v = *(const float4*)(hrow + (kk - H_));
                    v.x *= hmask; v.y *= hmask; v.z *= hmask; v.w *= hmask;
                }
            }
            aR[h] = v;
        }
    };
    auto loadB = [&](int k0) {
        const float* wp = Wp + ((size_t)((k0 >> 3) + ks) * G4 + (bn * BN + lm)) * 8;
        bR[0] = *(const float4*)(wp);
        bR[1] = *(const float4*)(wp + 4);
    };
    auto sts = [&]() {
        #pragma unroll
        for (int h = 0; h < 2; h++) {
            int kr = ks * 8 + h * 4;
            As[kr + 0][lm] = tf32_bits(aR[h].x);
            As[kr + 1][lm] = tf32_bits(aR[h].y);
            As[kr + 2][lm] = tf32_bits(aR[h].z);
            As[kr + 3][lm] = tf32_bits(aR[h].w);
            Bs[kr + 0][lm] = __float_as_uint(bR[h].x);   // pre-rounded tf32
            Bs[kr + 1][lm] = __float_as_uint(bR[h].y);
            Bs[kr + 2][lm] = __float_as_uint(bR[h].z);
            Bs[kr + 3][lm] = __float_as_uint(bR[h].w);
        }
    };

    float acc[2][2][4] = {};

    loadA(0); loadB(0);
    for (int k0 = 0; k0 < K; k0 += BKK) {
        __syncthreads();
        sts();
        __syncthreads();
        if (k0 + BKK < K) { loadA(k0 + BKK); loadB(k0 + BKK); }

        #pragma unroll
        for (int kk = 0; kk < BKK; kk += 8) {
            uint32_t a[2][4], b[2][2];
            #pragma unroll
            for (int mt = 0; mt < 2; mt++) {
                int m0 = wm * 32 + mt * 16 + gi;
                a[mt][0] = As[kk + tg][m0];
                a[mt][1] = As[kk + tg][m0 + 8];
                a[mt][2] = As[kk + tg + 4][m0];
                a[mt][3] = As[kk + tg + 4][m0 + 8];
            }
            #pragma unroll
            for (int nt = 0; nt < 2; nt++) {
                int n0 = wn * 16 + nt * 8 + gi;
                b[nt][0] = Bs[kk + tg][n0];
                b[nt][1] = Bs[kk + tg + 4][n0];
            }
            #pragma unroll
            for (int mt = 0; mt < 2; mt++)
                #pragma unroll
                for (int nt = 0; nt < 2; nt++)
                    asm volatile(
                        "mma.sync.aligned.m16n8k8.row.col.f32.tf32.tf32.f32 "
                        "{%0,%1,%2,%3},{%4,%5,%6,%7},{%8,%9},{%0,%1,%2,%3};"
                        : "+f"(acc[mt][nt][0]), "+f"(acc[mt][nt][1]),
                          "+f"(acc[mt][nt][2]), "+f"(acc[mt][nt][3])
                        : "r"(a[mt][0]), "r"(a[mt][1]), "r"(a[mt][2]), "r"(a[mt][3]),
                          "r"(b[nt][0]), "r"(b[nt][1]));
        }
    }

    // ---- fused LSTM cell epilogue ----
    // C frag: c0/c1 = (row gi, cols 2tg,2tg+1); c2/c3 = (row gi+8, same cols)
    // n-tile 0 cols 2tg,2tg+1 = (i,f) of unit u=tg; n-tile 1 (+8) = (g,o)
    const int g = bn * 4 + wn;
    const int j = g * 4 + tg;
    const float bi = bp[g * 16 + 2 * tg];
    const float bf = bp[g * 16 + 2 * tg + 1];
    const float bg = bp[g * 16 + 8 + 2 * tg];
    const float bo = bp[g * 16 + 9 + 2 * tg];

    #pragma unroll
    for (int mt = 0; mt < 2; mt++)
        #pragma unroll
        for (int rr = 0; rr < 2; rr++) {
            int b = bm * BM + wm * 32 + mt * 16 + rr * 8 + gi;
            float ig = acc[mt][0][rr * 2 + 0] + bi;
            float fg = acc[mt][0][rr * 2 + 1] + bf;
            float gg = acc[mt][1][rr * 2 + 0] + bg;
            float og = acc[mt][1][rr * 2 + 1] + bo;
            float si = 1.0f / (1.0f + expf(-ig));
            float sf = 1.0f / (1.0f + expf(-fg));
            float so = 1.0f / (1.0f + expf(-og));
            float tgh = tanhf(gg);
            float cold = is_init[b * T_ + t] ? 0.0f : cbuf[b * H_ + j];
            float cn = sf * cold + si * tgh;
            float hn = so * tanhf(cn);
            cbuf[b * H_ + j]  = cn;
            hnext[b * H_ + j] = hn;
            if (LAYER == 1)
                out[(size_t)b * T_ * H_ + (size_t)t * H_ + j] = hn;
        }
}

// ---------------- finalize: pack h_n, c_n after output ----------------
__global__ void finalize_kernel(float* __restrict__ out)
{
    const size_t off1 = (size_t)B_ * T_ * H_;
    const size_t off2 = off1 + (size_t)B_ * 2 * H_;
    int stride = gridDim.x * blockDim.x;
    for (int idx = blockIdx.x * blockDim.x + threadIdx.x; idx < B_ * H_; idx += stride) {
        int b = idx / H_, j = idx - b * H_;
        out[off1 + (size_t)b * 2 * H_ + j]      = g_h0[0][idx];  // T even -> ping 0
        out[off1 + (size_t)b * 2 * H_ + H_ + j] = g_h1[0][idx];
        out[off2 + (size_t)b * 2 * H_ + j]      = g_c0[idx];
        out[off2 + (size_t)b * 2 * H_ + H_ + j] = g_c1[idx];
    }
}

extern "C" void kernel_launch(void* const* d_in, const int* in_sizes, int n_in,
                              void* d_out, int out_size)
{
    const float* input   = (const float*)d_in[0];
    const int*   is_init = (const int*)d_in[1];
    const float* h       = (const float*)d_in[2];
    const float* c       = (const float*)d_in[3];
    const float* Wih0    = (const float*)d_in[4];
    const float* Whh0    = (const float*)d_in[5];
    const float* bih0    = (const float*)d_in[6];
    const float* bhh0    = (const float*)d_in[7];
    const float* Wih1    = (const float*)d_in[8];
    const float* Whh1    = (const float*)d_in[9];
    const float* bih1    = (const float*)d_in[10];
    const float* bhh1    = (const float*)d_in[11];
    float* out = (float*)d_out;

    permute_kernel<<<296, 256>>>(Wih0, Whh0, bih0, bhh0, Wih1, Whh1, bih1, bhh1);
    init_state_kernel<<<148, 256>>>(h, c);

    dim3 grid(G4 / BN, B_ / BM);   // (32, 4) = 128 blocks, 256 threads
    for (int t = 0; t < T_; t++) {
        lstm_step_kernel<0><<<grid, 256>>>(input, is_init, out, t);
        lstm_step_kernel<1><<<grid, 256>>>(input, is_init, out, t);
    }

    finalize_kernel<<<148, 256>>>(out);
}

// round 5
// speedup vs baseline: 2.0341x; 1.1529x over previous
#include <cuda_runtime.h>
#include <math.h>
#include <stdint.h>

// Problem dims
#define B_  256
#define T_  128
#define I_  256
#define H_  512
#define G4  2048   // 4*H
#define K0  768    // I + H
#define K1  1024   // H + H

// GEMM tile
#define BM  64
#define BN  64
#define BKK 32     // k per smem stage
#define SP  72     // smem row stride (8tg+gi banking -> conflict-free frag loads)

#define SMEM_STAGE (BKK * SP)          // words per stage per array
#define SMEM_BYTES (2 * SMEM_STAGE * 2 * 4)   // 2 bufs * (As+Bs) * 4B = 73728

// ---------------- scratch ----------------
__device__ float g_W0p[(K0/8) * G4 * 8];   // 6 MB, [k/8][p][k%8], tf32-rounded
__device__ float g_W1p[(K1/8) * G4 * 8];   // 8 MB
__device__ float g_b0p[G4];
__device__ float g_b1p[G4];
__device__ float g_h0[2][B_ * H_];
__device__ float g_h1[2][B_ * H_];
__device__ float g_c0[B_ * H_];
__device__ float g_c1[B_ * H_];

// column permutation: p -> original gate row q*H + j
__device__ __forceinline__ int p2norig(int p) {
    int g = p >> 4, pp = p & 15;
    int q = (pp < 8) ? (pp & 1) : (2 + (pp & 1));
    int u = (pp < 8) ? (pp >> 1) : ((pp - 8) >> 1);
    return q * H_ + g * 4 + u;
}

__device__ __forceinline__ uint32_t tf32_bits(float x) {
    uint32_t u;
    asm("cvt.rna.tf32.f32 %0, %1;" : "=r"(u) : "f"(x));
    return u;
}

// ---------------- prologue: permute + tf32-round + k-slice weights ----------------
__global__ void permute_kernel(const float* __restrict__ Wih0, const float* __restrict__ Whh0,
                               const float* __restrict__ bih0, const float* __restrict__ bhh0,
                               const float* __restrict__ Wih1, const float* __restrict__ Whh1,
                               const float* __restrict__ bih1, const float* __restrict__ bhh1)
{
    int stride = gridDim.x * blockDim.x;
    int tid0 = blockIdx.x * blockDim.x + threadIdx.x;

    for (int idx = tid0; idx < (K0/8) * G4 * 8; idx += stride) {
        int ki = idx & 7;
        int rest = idx >> 3;
        int p = rest & (G4 - 1);
        int kg = rest >> 11;
        int k = kg * 8 + ki;
        int norig = p2norig(p);
        float v = (k < I_) ? Wih0[norig * I_ + k] : Whh0[norig * H_ + (k - I_)];
        g_W0p[idx] = __uint_as_float(tf32_bits(v));
    }
    for (int idx = tid0; idx < (K1/8) * G4 * 8; idx += stride) {
        int ki = idx & 7;
        int rest = idx >> 3;
        int p = rest & (G4 - 1);
        int kg = rest >> 11;
        int k = kg * 8 + ki;
        int norig = p2norig(p);
        float v = (k < H_) ? Wih1[norig * H_ + k] : Whh1[norig * H_ + (k - H_)];
        g_W1p[idx] = __uint_as_float(tf32_bits(v));
    }
    for (int p = tid0; p < G4; p += stride) {
        int norig = p2norig(p);
        g_b0p[p] = bih0[norig] + bhh0[norig];
        g_b1p[p] = bih1[norig] + bhh1[norig];
    }
}

__global__ void init_state_kernel(const float* __restrict__ h, const float* __restrict__ c)
{
    int stride = gridDim.x * blockDim.x;
    for (int idx = blockIdx.x * blockDim.x + threadIdx.x; idx < B_ * H_; idx += stride) {
        int b = idx / H_, j = idx - b * H_;
        g_h0[0][idx] = h[b * 2 * H_ + j];
        g_h1[0][idx] = h[b * 2 * H_ + H_ + j];
        g_c0[idx]    = c[b * 2 * H_ + j];
        g_c1[idx]    = c[b * 2 * H_ + H_ + j];
    }
}

// ---------------- fused tf32 mma GEMM + LSTM cell (one layer, one timestep) ----------------
template<int LAYER>
__device__ __forceinline__ void lstm_step_body(
    uint32_t* __restrict__ smem,
    const float* __restrict__ input,
    const int* __restrict__ is_init,
    float* __restrict__ out,
    int t)
{
    constexpr int K = (LAYER == 0) ? K0 : K1;
    const float* Wp = (LAYER == 0) ? g_W0p : g_W1p;
    const float* bp = (LAYER == 0) ? g_b0p : g_b1p;
    const int ping = t & 1;
    const float* hprev = (LAYER == 0) ? g_h0[ping] : g_h1[ping];
    const float* h0new = g_h0[ping ^ 1];
    float* hnext = (LAYER == 0) ? g_h0[ping ^ 1] : g_h1[ping ^ 1];
    float* cbuf  = (LAYER == 0) ? g_c0 : g_c1;

    uint32_t* As = smem;                       // [buf][k][m]
    uint32_t* Bs = smem + 2 * SMEM_STAGE;      // [buf][k][n]

    const int tid = threadIdx.x;
    const int bn = blockIdx.x;
    const int bm = blockIdx.y;
    const int wid = tid >> 5, lane = tid & 31;
    const int wm = wid >> 2;
    const int wn = wid & 3;
    const int gi = lane >> 2;
    const int tg = lane & 3;

    const int lm = tid & 63;
    const int ks = tid >> 6;

    const int gb_l = bm * BM + lm;
    const float hmask = is_init[gb_l * T_ + t] ? 0.0f : 1.0f;
    const float* xrow  = input + (size_t)gb_l * T_ * I_ + (size_t)t * I_;
    const float* hrow  = hprev + gb_l * H_;
    const float* h0row = h0new + gb_l * H_;

    float4 aR[2], bR[2];

    auto loadA = [&](int k0) {
        #pragma unroll
        for (int h = 0; h < 2; h++) {
            int kk = k0 + ks * 8 + h * 4;
            float4 v;
            if (LAYER == 0) {
                if (kk < I_) v = *(const float4*)(xrow + kk);
                else {
                    v = *(const float4*)(hrow + (kk - I_));
                    v.x *= hmask; v.y *= hmask; v.z *= hmask; v.w *= hmask;
                }
            } else {
                if (kk < H_) v = *(const float4*)(h0row + kk);
                else {
                    v = *(const float4*)(hrow + (kk - H_));
                    v.x *= hmask; v.y *= hmask; v.z *= hmask; v.w *= hmask;
                }
            }
            aR[h] = v;
        }
    };
    auto loadB = [&](int k0) {
        const float* wp = Wp + ((size_t)((k0 >> 3) + ks) * G4 + (bn * BN + lm)) * 8;
        bR[0] = *(const float4*)(wp);
        bR[1] = *(const float4*)(wp + 4);
    };
    auto sts = [&](int buf) {
        uint32_t* Ab = As + buf * SMEM_STAGE;
        uint32_t* Bb = Bs + buf * SMEM_STAGE;
        #pragma unroll
        for (int h = 0; h < 2; h++) {
            int kr = ks * 8 + h * 4;
            Ab[(kr + 0) * SP + lm] = tf32_bits(aR[h].x);
            Ab[(kr + 1) * SP + lm] = tf32_bits(aR[h].y);
            Ab[(kr + 2) * SP + lm] = tf32_bits(aR[h].z);
            Ab[(kr + 3) * SP + lm] = tf32_bits(aR[h].w);
            Bb[(kr + 0) * SP + lm] = __float_as_uint(bR[h].x);
            Bb[(kr + 1) * SP + lm] = __float_as_uint(bR[h].y);
            Bb[(kr + 2) * SP + lm] = __float_as_uint(bR[h].z);
            Bb[(kr + 3) * SP + lm] = __float_as_uint(bR[h].w);
        }
    };

    float acc[2][2][4] = {};

    loadA(0); loadB(0);
    sts(0);
    __syncthreads();

    int buf = 0;
    for (int k0 = 0; k0 < K; k0 += BKK) {
        const bool has_next = (k0 + BKK < K);
        if (has_next) { loadA(k0 + BKK); loadB(k0 + BKK); }

        const uint32_t* Ab = As + buf * SMEM_STAGE;
        const uint32_t* Bb = Bs + buf * SMEM_STAGE;
        #pragma unroll
        for (int kk = 0; kk < BKK; kk += 8) {
            uint32_t a[2][4], b[2][2];
            #pragma unroll
            for (int mt = 0; mt < 2; mt++) {
                int m0 = wm * 32 + mt * 16 + gi;
                a[mt][0] = Ab[(kk + tg) * SP + m0];
                a[mt][1] = Ab[(kk + tg) * SP + m0 + 8];
                a[mt][2] = Ab[(kk + tg + 4) * SP + m0];
                a[mt][3] = Ab[(kk + tg + 4) * SP + m0 + 8];
            }
            #pragma unroll
            for (int nt = 0; nt < 2; nt++) {
                int n0 = wn * 16 + nt * 8 + gi;
                b[nt][0] = Bb[(kk + tg) * SP + n0];
                b[nt][1] = Bb[(kk + tg + 4) * SP + n0];
            }
            #pragma unroll
            for (int mt = 0; mt < 2; mt++)
                #pragma unroll
                for (int nt = 0; nt < 2; nt++)
                    asm volatile(
                        "mma.sync.aligned.m16n8k8.row.col.f32.tf32.tf32.f32 "
                        "{%0,%1,%2,%3},{%4,%5,%6,%7},{%8,%9},{%0,%1,%2,%3};"
                        : "+f"(acc[mt][nt][0]), "+f"(acc[mt][nt][1]),
                          "+f"(acc[mt][nt][2]), "+f"(acc[mt][nt][3])
                        : "r"(a[mt][0]), "r"(a[mt][1]), "r"(a[mt][2]), "r"(a[mt][3]),
                          "r"(b[nt][0]), "r"(b[nt][1]));
        }

        if (has_next) sts(buf ^ 1);
        __syncthreads();
        buf ^= 1;
    }

    // ---- fused LSTM cell epilogue ----
    const int g = bn * 4 + wn;
    const int j = g * 4 + tg;
    const float bi = bp[g * 16 + 2 * tg];
    const float bf = bp[g * 16 + 2 * tg + 1];
    const float bg = bp[g * 16 + 8 + 2 * tg];
    const float bo = bp[g * 16 + 9 + 2 * tg];

    #pragma unroll
    for (int mt = 0; mt < 2; mt++)
        #pragma unroll
        for (int rr = 0; rr < 2; rr++) {
            int b = bm * BM + wm * 32 + mt * 16 + rr * 8 + gi;
            float ig = acc[mt][0][rr * 2 + 0] + bi;
            float fg = acc[mt][0][rr * 2 + 1] + bf;
            float gg = acc[mt][1][rr * 2 + 0] + bg;
            float og = acc[mt][1][rr * 2 + 1] + bo;
            float si = 1.0f / (1.0f + expf(-ig));
            float sf = 1.0f / (1.0f + expf(-fg));
            float so = 1.0f / (1.0f + expf(-og));
            float tgh = tanhf(gg);
            float cold = is_init[b * T_ + t] ? 0.0f : cbuf[b * H_ + j];
            float cn = sf * cold + si * tgh;
            float hn = so * tanhf(cn);
            cbuf[b * H_ + j]  = cn;
            hnext[b * H_ + j] = hn;
            if (LAYER == 1)
                out[(size_t)b * T_ * H_ + (size_t)t * H_ + j] = hn;
        }
}

// Wavefront-fused launch s: z=0 -> layer0(time s), z=1 -> layer1(time s-1).
// The two are independent: layer1(s-1) reads g_h0[s&1] which layer0(s) only reads.
__global__ void __launch_bounds__(256, 2) fused_step_kernel(
    const float* __restrict__ input,
    const int* __restrict__ is_init,
    float* __restrict__ out,
    int s)
{
    extern __shared__ uint32_t smem[];
    if (blockIdx.z == 0) {
        if (s < T_) lstm_step_body<0>(smem, input, is_init, out, s);
    } else {
        if (s >= 1) lstm_step_body<1>(smem, input, is_init, out, s - 1);
    }
}

// ---------------- finalize: pack h_n, c_n after output ----------------
__global__ void finalize_kernel(float* __restrict__ out)
{
    const size_t off1 = (size_t)B_ * T_ * H_;
    const size_t off2 = off1 + (size_t)B_ * 2 * H_;
    int stride = gridDim.x * blockDim.x;
    for (int idx = blockIdx.x * blockDim.x + threadIdx.x; idx < B_ * H_; idx += stride) {
        int b = idx / H_, j = idx - b * H_;
        out[off1 + (size_t)b * 2 * H_ + j]      = g_h0[0][idx];  // T even -> ping 0
        out[off1 + (size_t)b * 2 * H_ + H_ + j] = g_h1[0][idx];
        out[off2 + (size_t)b * 2 * H_ + j]      = g_c0[idx];
        out[off2 + (size_t)b * 2 * H_ + H_ + j] = g_c1[idx];
    }
}

extern "C" void kernel_launch(void* const* d_in, const int* in_sizes, int n_in,
                              void* d_out, int out_size)
{
    const float* input   = (const float*)d_in[0];
    const int*   is_init = (const int*)d_in[1];
    const float* h       = (const float*)d_in[2];
    const float* c       = (const float*)d_in[3];
    const float* Wih0    = (const float*)d_in[4];
    const float* Whh0    = (const float*)d_in[5];
    const float* bih0    = (const float*)d_in[6];
    const float* bhh0    = (const float*)d_in[7];
    const float* Wih1    = (const float*)d_in[8];
    const float* Whh1    = (const float*)d_in[9];
    const float* bih1    = (const float*)d_in[10];
    const float* bhh1    = (const float*)d_in[11];
    float* out = (float*)d_out;

    static bool attr_set = false;
    if (!attr_set) {
        cudaFuncSetAttribute(fused_step_kernel,
                             cudaFuncAttributeMaxDynamicSharedMemorySize, SMEM_BYTES);
        attr_set = true;
    }

    permute_kernel<<<296, 256>>>(Wih0, Whh0, bih0, bhh0, Wih1, Whh1, bih1, bhh1);
    init_state_kernel<<<148, 256>>>(h, c);

    dim3 grid(G4 / BN, B_ / BM, 2);   // (32, 4, 2) = 256 blocks
    for (int s = 0; s <= T_; s++)
        fused_step_kernel<<<grid, 256, SMEM_BYTES>>>(input, is_init, out, s);

    finalize_kernel<<<148, 256>>>(out);
}

// round 6
// speedup vs baseline: 2.4343x; 1.1967x over previous
#include <cuda_runtime.h>
#include <math.h>
#include <stdint.h>

// Problem dims
#define B_  256
#define T_  128
#define I_  256
#define H_  512
#define G4  2048   // 4*H
#define K0  768    // I + H
#define K1  1024   // H + H

// GEMM tile: block 64(m) x 128(n), warp 32x32, BK stage 32
#define BM  64
#define BN  128
#define BKK 32
#define SPA 72     // A smem stride (banks 8tg+gi -> conflict-free)
#define SPB 136    // B smem stride (136 % 32 == 8 -> conflict-free)

#define A_STAGE (BKK * SPA)            // 2304 words
#define B_STAGE (BKK * SPB)            // 4352 words
#define SMEM_WORDS (2 * (A_STAGE + B_STAGE))
#define SMEM_BYTES (SMEM_WORDS * 4)    // 53248 B

// ---------------- scratch ----------------
__device__ float g_W0p[(K0/8) * G4 * 8];   // [k/8][p][k%8], tf32-rounded
__device__ float g_W1p[(K1/8) * G4 * 8];
__device__ float g_b0p[G4];
__device__ float g_b1p[G4];
__device__ float g_h0[2][B_ * H_];
__device__ float g_h1[2][B_ * H_];
__device__ float g_c0[B_ * H_];
__device__ float g_c1[B_ * H_];

// column permutation: p -> original gate row q*H + j  (groups of 16 cols = 4 units)
__device__ __forceinline__ int p2norig(int p) {
    int g = p >> 4, pp = p & 15;
    int q = (pp < 8) ? (pp & 1) : (2 + (pp & 1));
    int u = (pp < 8) ? (pp >> 1) : ((pp - 8) >> 1);
    return q * H_ + g * 4 + u;
}

__device__ __forceinline__ uint32_t tf32_bits(float x) {
    uint32_t u;
    asm("cvt.rna.tf32.f32 %0, %1;" : "=r"(u) : "f"(x));
    return u;
}

// ---------------- prologue ----------------
__global__ void permute_kernel(const float* __restrict__ Wih0, const float* __restrict__ Whh0,
                               const float* __restrict__ bih0, const float* __restrict__ bhh0,
                               const float* __restrict__ Wih1, const float* __restrict__ Whh1,
                               const float* __restrict__ bih1, const float* __restrict__ bhh1)
{
    int stride = gridDim.x * blockDim.x;
    int tid0 = blockIdx.x * blockDim.x + threadIdx.x;

    for (int idx = tid0; idx < (K0/8) * G4 * 8; idx += stride) {
        int ki = idx & 7;
        int rest = idx >> 3;
        int p = rest & (G4 - 1);
        int kg = rest >> 11;
        int k = kg * 8 + ki;
        int norig = p2norig(p);
        float v = (k < I_) ? Wih0[norig * I_ + k] : Whh0[norig * H_ + (k - I_)];
        g_W0p[idx] = __uint_as_float(tf32_bits(v));
    }
    for (int idx = tid0; idx < (K1/8) * G4 * 8; idx += stride) {
        int ki = idx & 7;
        int rest = idx >> 3;
        int p = rest & (G4 - 1);
        int kg = rest >> 11;
        int k = kg * 8 + ki;
        int norig = p2norig(p);
        float v = (k < H_) ? Wih1[norig * H_ + k] : Whh1[norig * H_ + (k - H_)];
        g_W1p[idx] = __uint_as_float(tf32_bits(v));
    }
    for (int p = tid0; p < G4; p += stride) {
        int norig = p2norig(p);
        g_b0p[p] = bih0[norig] + bhh0[norig];
        g_b1p[p] = bih1[norig] + bhh1[norig];
    }
}

__global__ void init_state_kernel(const float* __restrict__ h, const float* __restrict__ c)
{
    int stride = gridDim.x * blockDim.x;
    for (int idx = blockIdx.x * blockDim.x + threadIdx.x; idx < B_ * H_; idx += stride) {
        int b = idx / H_, j = idx - b * H_;
        g_h0[0][idx] = h[b * 2 * H_ + j];
        g_h1[0][idx] = h[b * 2 * H_ + H_ + j];
        g_c0[idx]    = c[b * 2 * H_ + j];
        g_c1[idx]    = c[b * 2 * H_ + H_ + j];
    }
}

// ---------------- fused tf32 mma GEMM + LSTM cell ----------------
template<int LAYER>
__device__ __forceinline__ void lstm_step_body(
    uint32_t* __restrict__ smem,
    const float* __restrict__ input,
    const int* __restrict__ is_init,
    float* __restrict__ out,
    int t)
{
    constexpr int K = (LAYER == 0) ? K0 : K1;
    const float* Wp = (LAYER == 0) ? g_W0p : g_W1p;
    const float* bp = (LAYER == 0) ? g_b0p : g_b1p;
    const int ping = t & 1;
    const float* hprev = (LAYER == 0) ? g_h0[ping] : g_h1[ping];
    const float* h0new = g_h0[ping ^ 1];
    float* hnext = (LAYER == 0) ? g_h0[ping ^ 1] : g_h1[ping ^ 1];
    float* cbuf  = (LAYER == 0) ? g_c0 : g_c1;

    uint32_t* As = smem;                     // [buf][k][m] stride SPA
    uint32_t* Bs = smem + 2 * A_STAGE;       // [buf][k][n] stride SPB

    const int tid = threadIdx.x;
    const int bn = blockIdx.x;               // 0..15 (128 cols each)
    const int bm = blockIdx.y;               // 0..3  (64 rows each)
    const int wid = tid >> 5, lane = tid & 31;
    const int wm = wid >> 2;                 // 0..1
    const int wn = wid & 3;                  // 0..3
    const int gi = lane >> 2;                // 0..7
    const int tg = lane & 3;                 // 0..3

    // A loader: row lmA (0..63), k-slice ksA (0..3) of 8
    const int lmA = tid & 63;
    const int ksA = tid >> 6;
    // B loader: col lmB (0..127), kg-pair ksB (0..1)
    const int lmB = tid & 127;
    const int ksB = tid >> 7;

    const int gb_l = bm * BM + lmA;
    const float hmask = is_init[gb_l * T_ + t] ? 0.0f : 1.0f;
    const float* xrow  = input + (size_t)gb_l * T_ * I_ + (size_t)t * I_;
    const float* hrow  = hprev + gb_l * H_;
    const float* h0row = h0new + gb_l * H_;

    float4 aR[2], bR[4];

    auto loadA = [&](int k0) {
        #pragma unroll
        for (int hh = 0; hh < 2; hh++) {
            int kk = k0 + ksA * 8 + hh * 4;
            float4 v;
            if (LAYER == 0) {
                if (kk < I_) v = *(const float4*)(xrow + kk);
                else {
                    v = *(const float4*)(hrow + (kk - I_));
                    v.x *= hmask; v.y *= hmask; v.z *= hmask; v.w *= hmask;
                }
            } else {
                if (kk < H_) v = *(const float4*)(h0row + kk);
                else {
                    v = *(const float4*)(hrow + (kk - H_));
                    v.x *= hmask; v.y *= hmask; v.z *= hmask; v.w *= hmask;
                }
            }
            aR[hh] = v;
        }
    };
    auto loadB = [&](int k0) {
        #pragma unroll
        for (int hh = 0; hh < 2; hh++) {
            int kg = (k0 >> 3) + ksB * 2 + hh;
            const float* wp = Wp + ((size_t)kg * G4 + (bn * BN + lmB)) * 8;
            bR[hh * 2 + 0] = *(const float4*)(wp);
            bR[hh * 2 + 1] = *(const float4*)(wp + 4);
        }
    };
    auto sts = [&](int buf) {
        uint32_t* Ab = As + buf * A_STAGE;
        uint32_t* Bb = Bs + buf * B_STAGE;
        #pragma unroll
        for (int hh = 0; hh < 2; hh++) {
            int kr = ksA * 8 + hh * 4;
            Ab[(kr + 0) * SPA + lmA] = tf32_bits(aR[hh].x);
            Ab[(kr + 1) * SPA + lmA] = tf32_bits(aR[hh].y);
            Ab[(kr + 2) * SPA + lmA] = tf32_bits(aR[hh].z);
            Ab[(kr + 3) * SPA + lmA] = tf32_bits(aR[hh].w);
        }
        #pragma unroll
        for (int hh = 0; hh < 2; hh++) {
            int kr = (ksB * 2 + hh) * 8;
            const float4 v0 = bR[hh * 2 + 0], v1 = bR[hh * 2 + 1];
            Bb[(kr + 0) * SPB + lmB] = __float_as_uint(v0.x);
            Bb[(kr + 1) * SPB + lmB] = __float_as_uint(v0.y);
            Bb[(kr + 2) * SPB + lmB] = __float_as_uint(v0.z);
            Bb[(kr + 3) * SPB + lmB] = __float_as_uint(v0.w);
            Bb[(kr + 4) * SPB + lmB] = __float_as_uint(v1.x);
            Bb[(kr + 5) * SPB + lmB] = __float_as_uint(v1.y);
            Bb[(kr + 6) * SPB + lmB] = __float_as_uint(v1.z);
            Bb[(kr + 7) * SPB + lmB] = __float_as_uint(v1.w);
        }
    };

    float acc[2][4][4] = {};

    loadA(0); loadB(0);
    sts(0);
    __syncthreads();

    int buf = 0;
    for (int k0 = 0; k0 < K; k0 += BKK) {
        const bool has_next = (k0 + BKK < K);
        if (has_next) { loadA(k0 + BKK); loadB(k0 + BKK); }

        const uint32_t* Ab = As + buf * A_STAGE;
        const uint32_t* Bb = Bs + buf * B_STAGE;
        #pragma unroll
        for (int kk = 0; kk < BKK; kk += 8) {
            uint32_t a[2][4], b[4][2];
            #pragma unroll
            for (int mt = 0; mt < 2; mt++) {
                int m0 = wm * 32 + mt * 16 + gi;
                a[mt][0] = Ab[(kk + tg) * SPA + m0];
                a[mt][1] = Ab[(kk + tg) * SPA + m0 + 8];
                a[mt][2] = Ab[(kk + tg + 4) * SPA + m0];
                a[mt][3] = Ab[(kk + tg + 4) * SPA + m0 + 8];
            }
            #pragma unroll
            for (int nt = 0; nt < 4; nt++) {
                int n0 = wn * 32 + nt * 8 + gi;
                b[nt][0] = Bb[(kk + tg) * SPB + n0];
                b[nt][1] = Bb[(kk + tg + 4) * SPB + n0];
            }
            #pragma unroll
            for (int mt = 0; mt < 2; mt++)
                #pragma unroll
                for (int nt = 0; nt < 4; nt++)
                    asm volatile(
                        "mma.sync.aligned.m16n8k8.row.col.f32.tf32.tf32.f32 "
                        "{%0,%1,%2,%3},{%4,%5,%6,%7},{%8,%9},{%0,%1,%2,%3};"
                        : "+f"(acc[mt][nt][0]), "+f"(acc[mt][nt][1]),
                          "+f"(acc[mt][nt][2]), "+f"(acc[mt][nt][3])
                        : "r"(a[mt][0]), "r"(a[mt][1]), "r"(a[mt][2]), "r"(a[mt][3]),
                          "r"(b[nt][0]), "r"(b[nt][1]));
        }

        if (has_next) sts(buf ^ 1);
        __syncthreads();
        buf ^= 1;
    }

    // ---- fused LSTM cell epilogue ----
    // Warp covers 32 cols = 2 groups of 16. gp selects group; nt=2gp -> (i,f), 2gp+1 -> (g,o).
    #pragma unroll
    for (int gp = 0; gp < 2; gp++) {
        const int g = bn * 8 + wn * 2 + gp;
        const int j = g * 4 + tg;
        const float bi = bp[g * 16 + 2 * tg];
        const float bf = bp[g * 16 + 2 * tg + 1];
        const float bg = bp[g * 16 + 8 + 2 * tg];
        const float bo = bp[g * 16 + 9 + 2 * tg];

        #pragma unroll
        for (int mt = 0; mt < 2; mt++)
            #pragma unroll
            for (int rr = 0; rr < 2; rr++) {
                int b = bm * BM + wm * 32 + mt * 16 + rr * 8 + gi;
                float ig = acc[mt][2 * gp + 0][rr * 2 + 0] + bi;
                float fg = acc[mt][2 * gp + 0][rr * 2 + 1] + bf;
                float gg = acc[mt][2 * gp + 1][rr * 2 + 0] + bg;
                float og = acc[mt][2 * gp + 1][rr * 2 + 1] + bo;
                float si = 1.0f / (1.0f + expf(-ig));
                float sf = 1.0f / (1.0f + expf(-fg));
                float so = 1.0f / (1.0f + expf(-og));
                float tgh = tanhf(gg);
                float cold = is_init[b * T_ + t] ? 0.0f : cbuf[b * H_ + j];
                float cn = sf * cold + si * tgh;
                float hn = so * tanhf(cn);
                cbuf[b * H_ + j]  = cn;
                hnext[b * H_ + j] = hn;
                if (LAYER == 1)
                    out[(size_t)b * T_ * H_ + (size_t)t * H_ + j] = hn;
            }
    }
}

// Wavefront-fused launch s: z=0 -> layer0(time s), z=1 -> layer1(time s-1).
__global__ void __launch_bounds__(256, 1) fused_step_kernel(
    const float* __restrict__ input,
    const int* __restrict__ is_init,
    float* __restrict__ out,
    int s)
{
    extern __shared__ uint32_t smem[];
    if (blockIdx.z == 0) {
        if (s < T_) lstm_step_body<0>(smem, input, is_init, out, s);
    } else {
        if (s >= 1) lstm_step_body<1>(smem, input, is_init, out, s - 1);
    }
}

// ---------------- finalize ----------------
__global__ void finalize_kernel(float* __restrict__ out)
{
    const size_t off1 = (size_t)B_ * T_ * H_;
    const size_t off2 = off1 + (size_t)B_ * 2 * H_;
    int stride = gridDim.x * blockDim.x;
    for (int idx = blockIdx.x * blockDim.x + threadIdx.x; idx < B_ * H_; idx += stride) {
        int b = idx / H_, j = idx - b * H_;
        out[off1 + (size_t)b * 2 * H_ + j]      = g_h0[0][idx];  // T even -> ping 0
        out[off1 + (size_t)b * 2 * H_ + H_ + j] = g_h1[0][idx];
        out[off2 + (size_t)b * 2 * H_ + j]      = g_c0[idx];
        out[off2 + (size_t)b * 2 * H_ + H_ + j] = g_c1[idx];
    }
}

extern "C" void kernel_launch(void* const* d_in, const int* in_sizes, int n_in,
                              void* d_out, int out_size)
{
    const float* input   = (const float*)d_in[0];
    const int*   is_init = (const int*)d_in[1];
    const float* h       = (const float*)d_in[2];
    const float* c       = (const float*)d_in[3];
    const float* Wih0    = (const float*)d_in[4];
    const float* Whh0    = (const float*)d_in[5];
    const float* bih0    = (const float*)d_in[6];
    const float* bhh0    = (const float*)d_in[7];
    const float* Wih1    = (const float*)d_in[8];
    const float* Whh1    = (const float*)d_in[9];
    const float* bih1    = (const float*)d_in[10];
    const float* bhh1    = (const float*)d_in[11];
    float* out = (float*)d_out;

    static bool attr_set = false;
    if (!attr_set) {
        cudaFuncSetAttribute(fused_step_kernel,
                             cudaFuncAttributeMaxDynamicSharedMemorySize, SMEM_BYTES);
        attr_set = true;
    }

    permute_kernel<<<296, 256>>>(Wih0, Whh0, bih0, bhh0, Wih1, Whh1, bih1, bhh1);
    init_state_kernel<<<148, 256>>>(h, c);

    dim3 grid(G4 / BN, B_ / BM, 2);   // (16, 4, 2) = 128 blocks, single wave
    for (int s = 0; s <= T_; s++)
        fused_step_kernel<<<grid, 256, SMEM_BYTES>>>(input, is_init, out, s);

    finalize_kernel<<<148, 256>>>(out);
}

// round 7
// speedup vs baseline: 2.6137x; 1.0737x over previous
#include <cuda_runtime.h>
#include <math.h>
#include <stdint.h>

// Problem dims
#define B_  256
#define T_  128
#define I_  256
#define H_  512
#define G4  2048   // 4*H
#define K0  768    // I + H
#define K1  1024   // H + H

// GEMM tile: block 64(m) x 128(n), 8 warps (2m x 4n), warp 32x32, stage BK=32
#define BM  64
#define BN  128
#define BKK 32
#define SPK 36                       // k stride in smem (pad: banks 4*gi+tg, conflict-free)
#define DEPTH 4                      // smem ring buffers (3 in flight)

#define A_WORDS (BM * SPK)           // 2304
#define B_WORDS (BN * SPK)           // 4608
#define SMEM_BYTES (DEPTH * (A_WORDS + B_WORDS) * 4)   // 110592

// ---------------- scratch ----------------
__device__ float g_W0p[(K0/8) * G4 * 8];   // [k/8][p][k%8], tf32-rounded
__device__ float g_W1p[(K1/8) * G4 * 8];
__device__ float g_b0p[G4];
__device__ float g_b1p[G4];
__device__ float g_h0[2][B_ * H_];
__device__ float g_h1[2][B_ * H_];
__device__ float g_c0[B_ * H_];
__device__ float g_c1[B_ * H_];

// column permutation: p -> original gate row q*H + j  (groups of 16 cols = 4 units)
__device__ __forceinline__ int p2norig(int p) {
    int g = p >> 4, pp = p & 15;
    int q = (pp < 8) ? (pp & 1) : (2 + (pp & 1));
    int u = (pp < 8) ? (pp >> 1) : ((pp - 8) >> 1);
    return q * H_ + g * 4 + u;
}

__device__ __forceinline__ uint32_t tf32_bits(float x) {
    uint32_t u;
    asm("cvt.rna.tf32.f32 %0, %1;" : "=r"(u) : "f"(x));
    return u;
}

__device__ __forceinline__ void cp16(uint32_t dst, const void* src) {
    asm volatile("cp.async.cg.shared.global [%0], [%1], 16;" :: "r"(dst), "l"(src));
}

// ---------------- prologue ----------------
__global__ void permute_kernel(const float* __restrict__ Wih0, const float* __restrict__ Whh0,
                               const float* __restrict__ bih0, const float* __restrict__ bhh0,
                               const float* __restrict__ Wih1, const float* __restrict__ Whh1,
                               const float* __restrict__ bih1, const float* __restrict__ bhh1)
{
    int stride = gridDim.x * blockDim.x;
    int tid0 = blockIdx.x * blockDim.x + threadIdx.x;

    for (int idx = tid0; idx < (K0/8) * G4 * 8; idx += stride) {
        int ki = idx & 7;
        int rest = idx >> 3;
        int p = rest & (G4 - 1);
        int kg = rest >> 11;
        int k = kg * 8 + ki;
        int norig = p2norig(p);
        float v = (k < I_) ? Wih0[norig * I_ + k] : Whh0[norig * H_ + (k - I_)];
        g_W0p[idx] = __uint_as_float(tf32_bits(v));
    }
    for (int idx = tid0; idx < (K1/8) * G4 * 8; idx += stride) {
        int ki = idx & 7;
        int rest = idx >> 3;
        int p = rest & (G4 - 1);
        int kg = rest >> 11;
        int k = kg * 8 + ki;
        int norig = p2norig(p);
        float v = (k < H_) ? Wih1[norig * H_ + k] : Whh1[norig * H_ + (k - H_)];
        g_W1p[idx] = __uint_as_float(tf32_bits(v));
    }
    for (int p = tid0; p < G4; p += stride) {
        int norig = p2norig(p);
        g_b0p[p] = bih0[norig] + bhh0[norig];
        g_b1p[p] = bih1[norig] + bhh1[norig];
    }
}

__global__ void init_state_kernel(const float* __restrict__ h, const float* __restrict__ c)
{
    int stride = gridDim.x * blockDim.x;
    for (int idx = blockIdx.x * blockDim.x + threadIdx.x; idx < B_ * H_; idx += stride) {
        int b = idx / H_, j = idx - b * H_;
        g_h0[0][idx] = h[b * 2 * H_ + j];
        g_h1[0][idx] = h[b * 2 * H_ + H_ + j];
        g_c0[idx]    = c[b * 2 * H_ + j];
        g_c1[idx]    = c[b * 2 * H_ + H_ + j];
    }
}

// ---------------- fused tf32 mma GEMM + LSTM cell, cp.async 4-stage pipeline ----------------
template<int LAYER>
__device__ __forceinline__ void lstm_step_body(
    uint32_t* __restrict__ smem,
    const float* __restrict__ input,
    const int* __restrict__ is_init,
    float* __restrict__ out,
    int t)
{
    constexpr int K = (LAYER == 0) ? K0 : K1;
    constexpr int NSTAGE = K / BKK;                 // 24 or 32
    constexpr int BOUND  = (LAYER == 0) ? I_ : H_;  // stage-aligned x/h boundary
    const float* Wp = (LAYER == 0) ? g_W0p : g_W1p;
    const float* bp = (LAYER == 0) ? g_b0p : g_b1p;
    const int ping = t & 1;
    const float* hprev = (LAYER == 0) ? g_h0[ping] : g_h1[ping];
    const float* h0new = g_h0[ping ^ 1];
    float* hnext = (LAYER == 0) ? g_h0[ping ^ 1] : g_h1[ping ^ 1];
    float* cbuf  = (LAYER == 0) ? g_c0 : g_c1;

    const int tid = threadIdx.x;
    const int bn = blockIdx.x;               // 0..15 (128 gate cols)
    const int bm = blockIdx.y;               // 0..3  (64 batch rows)
    const int wid = tid >> 5, lane = tid & 31;
    const int wm = wid >> 2;                 // 0..1
    const int wn = wid & 3;                  // 0..3
    const int gi = lane >> 2;                // 0..7
    const int tg = lane & 3;                 // 0..3

    uint32_t sbase = (uint32_t)__cvta_generic_to_shared(smem);
    uint32_t sA = sbase;
    uint32_t sB = sbase + DEPTH * A_WORDS * 4;
    const uint32_t* AsP = smem;                       // [buf][m][k] stride SPK
    const uint32_t* BsP = smem + DEPTH * A_WORDS;     // [buf][n][k] stride SPK

    // producer: A 512 chunks of 16B (2/thread), B 1024 chunks (4/thread)
    auto issue = [&](int st) {
        const int k0 = st * BKK;
        const uint32_t aBuf = sA + (st & (DEPTH - 1)) * A_WORDS * 4;
        #pragma unroll
        for (int hh = 0; hh < 2; hh++) {
            int chunk = tid + 256 * hh;
            int m = chunk >> 3, kc = chunk & 7;
            int k = k0 + kc * 4;
            int gb = bm * BM + m;
            const float* src;
            if (LAYER == 0)
                src = (k < I_) ? (input + (size_t)gb * T_ * I_ + (size_t)t * I_ + k)
                               : (hprev + gb * H_ + (k - I_));
            else
                src = (k < H_) ? (h0new + gb * H_ + k)
                               : (hprev + gb * H_ + (k - H_));
            cp16(aBuf + (m * SPK + kc * 4) * 4, src);
        }
        const uint32_t bBuf = sB + (st & (DEPTH - 1)) * B_WORDS * 4;
        #pragma unroll
        for (int hh = 0; hh < 4; hh++) {
            int chunk = tid + 256 * hh;
            int n = chunk >> 3, kc = chunk & 7;
            int kg = (k0 >> 3) + (kc >> 1);
            const float* src = Wp + ((size_t)kg * G4 + bn * BN + n) * 8 + (kc & 1) * 4;
            cp16(bBuf + (n * SPK + kc * 4) * 4, src);
        }
    };

    // per-thread row masks for the h-region (rows this warp's A frags cover)
    float rmask[2][2];
    #pragma unroll
    for (int mt = 0; mt < 2; mt++)
        #pragma unroll
        for (int rr = 0; rr < 2; rr++) {
            int gbr = bm * BM + wm * 32 + mt * 16 + rr * 8 + gi;
            rmask[mt][rr] = is_init[gbr * T_ + t] ? 0.0f : 1.0f;
        }

    float acc[2][4][4] = {};

    issue(0); asm volatile("cp.async.commit_group;" ::: "memory");
    issue(1); asm volatile("cp.async.commit_group;" ::: "memory");
    issue(2); asm volatile("cp.async.commit_group;" ::: "memory");

    #pragma unroll 4
    for (int st = 0; st < NSTAGE; st++) {
        asm volatile("cp.async.wait_group 2;" ::: "memory");
        __syncthreads();                 // stage st ready; all reads of stage st-1 done

        if (st + 3 < NSTAGE) issue(st + 3);
        asm volatile("cp.async.commit_group;" ::: "memory");   // empty commit keeps count

        const int buf = st & (DEPTH - 1);
        const uint32_t* Ab = AsP + buf * A_WORDS;
        const uint32_t* Bb = BsP + buf * B_WORDS;
        const bool msk = (st * BKK >= BOUND);

        #pragma unroll
        for (int kk = 0; kk < BKK; kk += 8) {
            uint32_t a[2][4], b[4][2];
            #pragma unroll
            for (int mt = 0; mt < 2; mt++) {
                int m0 = wm * 32 + mt * 16 + gi;
                uint32_t r0 = Ab[m0 * SPK + kk + tg];
                uint32_t r2 = Ab[m0 * SPK + kk + tg + 4];
                uint32_t r1 = Ab[(m0 + 8) * SPK + kk + tg];
                uint32_t r3 = Ab[(m0 + 8) * SPK + kk + tg + 4];
                float w0 = msk ? rmask[mt][0] : 1.0f;
                float w1 = msk ? rmask[mt][1] : 1.0f;
                a[mt][0] = tf32_bits(__uint_as_float(r0) * w0);
                a[mt][1] = tf32_bits(__uint_as_float(r1) * w1);
                a[mt][2] = tf32_bits(__uint_as_float(r2) * w0);
                a[mt][3] = tf32_bits(__uint_as_float(r3) * w1);
            }
            #pragma unroll
            for (int nt = 0; nt < 4; nt++) {
                int n0 = wn * 32 + nt * 8 + gi;
                b[nt][0] = Bb[n0 * SPK + kk + tg];
                b[nt][1] = Bb[n0 * SPK + kk + tg + 4];
            }
            #pragma unroll
            for (int mt = 0; mt < 2; mt++)
                #pragma unroll
                for (int nt = 0; nt < 4; nt++)
                    asm volatile(
                        "mma.sync.aligned.m16n8k8.row.col.f32.tf32.tf32.f32 "
                        "{%0,%1,%2,%3},{%4,%5,%6,%7},{%8,%9},{%0,%1,%2,%3};"
                        : "+f"(acc[mt][nt][0]), "+f"(acc[mt][nt][1]),
                          "+f"(acc[mt][nt][2]), "+f"(acc[mt][nt][3])
                        : "r"(a[mt][0]), "r"(a[mt][1]), "r"(a[mt][2]), "r"(a[mt][3]),
                          "r"(b[nt][0]), "r"(b[nt][1]));
        }
    }

    // ---- fused LSTM cell epilogue ----
    #pragma unroll
    for (int gp = 0; gp < 2; gp++) {
        const int g = bn * 8 + wn * 2 + gp;
        const int j = g * 4 + tg;
        const float bi = bp[g * 16 + 2 * tg];
        const float bf = bp[g * 16 + 2 * tg + 1];
        const float bg = bp[g * 16 + 8 + 2 * tg];
        const float bo = bp[g * 16 + 9 + 2 * tg];

        #pragma unroll
        for (int mt = 0; mt < 2; mt++)
            #pragma unroll
            for (int rr = 0; rr < 2; rr++) {
                int b = bm * BM + wm * 32 + mt * 16 + rr * 8 + gi;
                float ig = acc[mt][2 * gp + 0][rr * 2 + 0] + bi;
                float fg = acc[mt][2 * gp + 0][rr * 2 + 1] + bf;
                float gg = acc[mt][2 * gp + 1][rr * 2 + 0] + bg;
                float og = acc[mt][2 * gp + 1][rr * 2 + 1] + bo;
                float si = 1.0f / (1.0f + expf(-ig));
                float sf = 1.0f / (1.0f + expf(-fg));
                float so = 1.0f / (1.0f + expf(-og));
                float tgh = tanhf(gg);
                float cold = is_init[b * T_ + t] ? 0.0f : cbuf[b * H_ + j];
                float cn = sf * cold + si * tgh;
                float hn = so * tanhf(cn);
                cbuf[b * H_ + j]  = cn;
                hnext[b * H_ + j] = hn;
                if (LAYER == 1)
                    out[(size_t)b * T_ * H_ + (size_t)t * H_ + j] = hn;
            }
    }
}

// Wavefront-fused launch s: z=0 -> layer0(time s), z=1 -> layer1(time s-1).
__global__ void __launch_bounds__(256, 1) fused_step_kernel(
    const float* __restrict__ input,
    const int* __restrict__ is_init,
    float* __restrict__ out,
    int s)
{
    extern __shared__ uint32_t smem[];
    if (blockIdx.z == 0) {
        if (s < T_) lstm_step_body<0>(smem, input, is_init, out, s);
    } else {
        if (s >= 1) lstm_step_body<1>(smem, input, is_init, out, s - 1);
    }
}

// ---------------- finalize ----------------
__global__ void finalize_kernel(float* __restrict__ out)
{
    const size_t off1 = (size_t)B_ * T_ * H_;
    const size_t off2 = off1 + (size_t)B_ * 2 * H_;
    int stride = gridDim.x * blockDim.x;
    for (int idx = blockIdx.x * blockDim.x + threadIdx.x; idx < B_ * H_; idx += stride) {
        int b = idx / H_, j = idx - b * H_;
        out[off1 + (size_t)b * 2 * H_ + j]      = g_h0[0][idx];  // T even -> ping 0
        out[off1 + (size_t)b * 2 * H_ + H_ + j] = g_h1[0][idx];
        out[off2 + (size_t)b * 2 * H_ + j]      = g_c0[idx];
        out[off2 + (size_t)b * 2 * H_ + H_ + j] = g_c1[idx];
    }
}

extern "C" void kernel_launch(void* const* d_in, const int* in_sizes, int n_in,
                              void* d_out, int out_size)
{
    const float* input   = (const float*)d_in[0];
    const int*   is_init = (const int*)d_in[1];
    const float* h       = (const float*)d_in[2];
    const float* c       = (const float*)d_in[3];
    const float* Wih0    = (const float*)d_in[4];
    const float* Whh0    = (const float*)d_in[5];
    const float* bih0    = (const float*)d_in[6];
    const float* bhh0    = (const float*)d_in[7];
    const float* Wih1    = (const float*)d_in[8];
    const float* Whh1    = (const float*)d_in[9];
    const float* bih1    = (const float*)d_in[10];
    const float* bhh1    = (const float*)d_in[11];
    float* out = (float*)d_out;

    static bool attr_set = false;
    if (!attr_set) {
        cudaFuncSetAttribute(fused_step_kernel,
                             cudaFuncAttributeMaxDynamicSharedMemorySize, SMEM_BYTES);
        attr_set = true;
    }

    permute_kernel<<<296, 256>>>(Wih0, Whh0, bih0, bhh0, Wih1, Whh1, bih1, bhh1);
    init_state_kernel<<<148, 256>>>(h, c);

    dim3 grid(G4 / BN, B_ / BM, 2);   // (16, 4, 2) = 128 blocks, single wave
    for (int s = 0; s <= T_; s++)
        fused_step_kernel<<<grid, 256, SMEM_BYTES>>>(input, is_init, out, s);

    finalize_kernel<<<148, 256>>>(out);
}

// round 8
// speedup vs baseline: 2.9828x; 1.1412x over previous
#include <cuda_runtime.h>
#include <math.h>
#include <stdint.h>

// Problem dims
#define B_  256
#define T_  128
#define I_  256
#define H_  512
#define G4  2048   // 4*H
#define K0  768    // I + H
#define K1  1024   // H + H

// GEMM tile: block 64(m) x 128(n), 8 warps (2m x 4n), warp 32x32, stage BK=32
#define BM  64
#define BN  128
#define BKK 32
#define SPK 36                       // k stride in smem (banks 4*gi+tg, conflict-free)
#define DEPTH 4                      // smem ring buffers (3 in flight)

#define A_WORDS (BM * SPK)           // 2304
#define B_WORDS (BN * SPK)           // 4608
#define SMEM_BYTES (DEPTH * (A_WORDS + B_WORDS) * 4)   // 110592

// ---------------- scratch ----------------
__device__ float g_W0p[(K0/8) * G4 * 8];   // [k/8][p][k%8], tf32-rounded
__device__ float g_W1p[(K1/8) * G4 * 8];
__device__ float g_b0p[G4];
__device__ float g_b1p[G4];
__device__ float g_x32[B_ * T_ * I_];      // tf32-rounded input
__device__ float g_h0 [2][B_ * H_];        // rounded, UNMASKED (layer1 input)
__device__ float g_h0m[2][B_ * H_];        // rounded, masked by next-step flag
__device__ float g_h1m[2][B_ * H_];
__device__ float g_c0[B_ * H_];
__device__ float g_c1[B_ * H_];
__device__ float g_h0f[B_ * H_];           // exact h(T-1) for h_n
__device__ float g_h1f[B_ * H_];

// column permutation: p -> original gate row q*H + j  (groups of 16 cols = 4 units)
__device__ __forceinline__ int p2norig(int p) {
    int g = p >> 4, pp = p & 15;
    int q = (pp < 8) ? (pp & 1) : (2 + (pp & 1));
    int u = (pp < 8) ? (pp >> 1) : ((pp - 8) >> 1);
    return q * H_ + g * 4 + u;
}

__device__ __forceinline__ uint32_t tf32_bits(float x) {
    uint32_t u;
    asm("cvt.rna.tf32.f32 %0, %1;" : "=r"(u) : "f"(x));
    return u;
}

__device__ __forceinline__ void cp16(uint32_t dst, const void* src) {
    asm volatile("cp.async.cg.shared.global [%0], [%1], 16;" :: "r"(dst), "l"(src));
}

// ---------------- prologue ----------------
__global__ void permute_kernel(const float* __restrict__ input,
                               const float* __restrict__ Wih0, const float* __restrict__ Whh0,
                               const float* __restrict__ bih0, const float* __restrict__ bhh0,
                               const float* __restrict__ Wih1, const float* __restrict__ Whh1,
                               const float* __restrict__ bih1, const float* __restrict__ bhh1)
{
    int stride = gridDim.x * blockDim.x;
    int tid0 = blockIdx.x * blockDim.x + threadIdx.x;

    for (int idx = tid0; idx < B_ * T_ * I_; idx += stride)
        g_x32[idx] = __uint_as_float(tf32_bits(input[idx]));

    for (int idx = tid0; idx < (K0/8) * G4 * 8; idx += stride) {
        int ki = idx & 7;
        int rest = idx >> 3;
        int p = rest & (G4 - 1);
        int kg = rest >> 11;
        int k = kg * 8 + ki;
        int norig = p2norig(p);
        float v = (k < I_) ? Wih0[norig * I_ + k] : Whh0[norig * H_ + (k - I_)];
        g_W0p[idx] = __uint_as_float(tf32_bits(v));
    }
    for (int idx = tid0; idx < (K1/8) * G4 * 8; idx += stride) {
        int ki = idx & 7;
        int rest = idx >> 3;
        int p = rest & (G4 - 1);
        int kg = rest >> 11;
        int k = kg * 8 + ki;
        int norig = p2norig(p);
        float v = (k < H_) ? Wih1[norig * H_ + k] : Whh1[norig * H_ + (k - H_)];
        g_W1p[idx] = __uint_as_float(tf32_bits(v));
    }
    for (int p = tid0; p < G4; p += stride) {
        int norig = p2norig(p);
        g_b0p[p] = bih0[norig] + bhh0[norig];
        g_b1p[p] = bih1[norig] + bhh1[norig];
    }
}

__global__ void init_state_kernel(const float* __restrict__ h, const float* __restrict__ c,
                                  const int* __restrict__ is_init)
{
    int stride = gridDim.x * blockDim.x;
    for (int idx = blockIdx.x * blockDim.x + threadIdx.x; idx < B_ * H_; idx += stride) {
        int b = idx / H_, j = idx - b * H_;
        float m0 = is_init[b * T_] ? 0.0f : 1.0f;
        g_h0m[0][idx] = __uint_as_float(tf32_bits(h[b * 2 * H_ + j])) * m0;
        g_h1m[0][idx] = __uint_as_float(tf32_bits(h[b * 2 * H_ + H_ + j])) * m0;
        g_c0[idx]     = c[b * 2 * H_ + j];
        g_c1[idx]     = c[b * 2 * H_ + H_ + j];
    }
}

// ---------------- fused tf32 mma GEMM + LSTM cell, cp.async 4-stage pipeline ----------------
template<int LAYER>
__device__ __forceinline__ void lstm_step_body(
    uint32_t* __restrict__ smem,
    const int* __restrict__ is_init,
    float* __restrict__ out,
    int t)
{
    constexpr int K = (LAYER == 0) ? K0 : K1;
    constexpr int NSTAGE = K / BKK;                 // 24 or 32
    const float* Wp = (LAYER == 0) ? g_W0p : g_W1p;
    const float* bp = (LAYER == 0) ? g_b0p : g_b1p;
    const int ping = t & 1;
    const float* hmsk = (LAYER == 0) ? g_h0m[ping] : g_h1m[ping];  // masked recurrence
    const float* h0u  = g_h0[ping ^ 1];                            // layer1 input (unmasked)
    float* cbuf = (LAYER == 0) ? g_c0 : g_c1;

    const int tid = threadIdx.x;
    const int bn = blockIdx.x;               // 0..15 (128 gate cols)
    const int bm = blockIdx.y;               // 0..3  (64 batch rows)
    const int wid = tid >> 5, lane = tid & 31;
    const int wm = wid >> 2;                 // 0..1
    const int wn = wid & 3;                  // 0..3
    const int gi = lane >> 2;                // 0..7
    const int tg = lane & 3;                 // 0..3

    uint32_t sbase = (uint32_t)__cvta_generic_to_shared(smem);
    uint32_t sA = sbase;
    uint32_t sB = sbase + DEPTH * A_WORDS * 4;
    const uint32_t* AsP = smem;                       // [buf][m][k] stride SPK
    const uint32_t* BsP = smem + DEPTH * A_WORDS;     // [buf][n][k] stride SPK

    auto issue = [&](int st) {
        const int k0 = st * BKK;
        const uint32_t aBuf = sA + (st & (DEPTH - 1)) * A_WORDS * 4;
        #pragma unroll
        for (int hh = 0; hh < 2; hh++) {
            int chunk = tid + 256 * hh;
            int m = chunk >> 3, kc = chunk & 7;
            int k = k0 + kc * 4;
            int gb = bm * BM + m;
            const float* src;
            if (LAYER == 0)
                src = (k < I_) ? (g_x32 + (size_t)gb * T_ * I_ + (size_t)t * I_ + k)
                               : (hmsk + gb * H_ + (k - I_));
            else
                src = (k < H_) ? (h0u + gb * H_ + k)
                               : (hmsk + gb * H_ + (k - H_));
            cp16(aBuf + (m * SPK + kc * 4) * 4, src);
        }
        const uint32_t bBuf = sB + (st & (DEPTH - 1)) * B_WORDS * 4;
        #pragma unroll
        for (int hh = 0; hh < 4; hh++) {
            int chunk = tid + 256 * hh;
            int n = chunk >> 3, kc = chunk & 7;
            int kg = (k0 >> 3) + (kc >> 1);
            const float* src = Wp + ((size_t)kg * G4 + bn * BN + n) * 8 + (kc & 1) * 4;
            cp16(bBuf + (n * SPK + kc * 4) * 4, src);
        }
    };

    float acc[2][4][4] = {};

    issue(0); asm volatile("cp.async.commit_group;" ::: "memory");
    issue(1); asm volatile("cp.async.commit_group;" ::: "memory");
    issue(2); asm volatile("cp.async.commit_group;" ::: "memory");

    #pragma unroll 4
    for (int st = 0; st < NSTAGE; st++) {
        asm volatile("cp.async.wait_group 2;" ::: "memory");
        __syncthreads();

        if (st + 3 < NSTAGE) issue(st + 3);
        asm volatile("cp.async.commit_group;" ::: "memory");

        const int buf = st & (DEPTH - 1);
        const uint32_t* Ab = AsP + buf * A_WORDS;
        const uint32_t* Bb = BsP + buf * B_WORDS;

        uint32_t a[2][2][4], b[2][4][2];
        auto ldfrag = [&](int kk, int pb) {
            #pragma unroll
            for (int mt = 0; mt < 2; mt++) {
                int m0 = wm * 32 + mt * 16 + gi;
                a[pb][mt][0] = Ab[m0 * SPK + kk + tg];
                a[pb][mt][1] = Ab[(m0 + 8) * SPK + kk + tg];
                a[pb][mt][2] = Ab[m0 * SPK + kk + tg + 4];
                a[pb][mt][3] = Ab[(m0 + 8) * SPK + kk + tg + 4];
            }
            #pragma unroll
            for (int nt = 0; nt < 4; nt++) {
                int n0 = wn * 32 + nt * 8 + gi;
                b[pb][nt][0] = Bb[n0 * SPK + kk + tg];
                b[pb][nt][1] = Bb[n0 * SPK + kk + tg + 4];
            }
        };

        ldfrag(0, 0);
        #pragma unroll
        for (int kq = 0; kq < 4; kq++) {
            if (kq < 3) ldfrag((kq + 1) * 8, (kq + 1) & 1);
            const int pb = kq & 1;
            #pragma unroll
            for (int mt = 0; mt < 2; mt++)
                #pragma unroll
                for (int nt = 0; nt < 4; nt++)
                    asm volatile(
                        "mma.sync.aligned.m16n8k8.row.col.f32.tf32.tf32.f32 "
                        "{%0,%1,%2,%3},{%4,%5,%6,%7},{%8,%9},{%0,%1,%2,%3};"
                        : "+f"(acc[mt][nt][0]), "+f"(acc[mt][nt][1]),
                          "+f"(acc[mt][nt][2]), "+f"(acc[mt][nt][3])
                        : "r"(a[pb][mt][0]), "r"(a[pb][mt][1]),
                          "r"(a[pb][mt][2]), "r"(a[pb][mt][3]),
                          "r"(b[pb][nt][0]), "r"(b[pb][nt][1]));
        }
    }

    // ---- fused LSTM cell epilogue ----
    float* h0u_w = g_h0[ping ^ 1];           // layer0 writes unmasked rounded h0(t)
    float* hm_w  = (LAYER == 0) ? g_h0m[ping ^ 1] : g_h1m[ping ^ 1];
    float* hf_w  = (LAYER == 0) ? g_h0f : g_h1f;

    #pragma unroll
    for (int gp = 0; gp < 2; gp++) {
        const int g = bn * 8 + wn * 2 + gp;
        const int j = g * 4 + tg;
        const float bi = bp[g * 16 + 2 * tg];
        const float bf = bp[g * 16 + 2 * tg + 1];
        const float bg = bp[g * 16 + 8 + 2 * tg];
        const float bo = bp[g * 16 + 9 + 2 * tg];

        #pragma unroll
        for (int mt = 0; mt < 2; mt++)
            #pragma unroll
            for (int rr = 0; rr < 2; rr++) {
                int b = bm * BM + wm * 32 + mt * 16 + rr * 8 + gi;
                float ig = acc[mt][2 * gp + 0][rr * 2 + 0] + bi;
                float fg = acc[mt][2 * gp + 0][rr * 2 + 1] + bf;
                float gg = acc[mt][2 * gp + 1][rr * 2 + 0] + bg;
                float og = acc[mt][2 * gp + 1][rr * 2 + 1] + bo;
                float si = 1.0f / (1.0f + expf(-ig));
                float sf = 1.0f / (1.0f + expf(-fg));
                float so = 1.0f / (1.0f + expf(-og));
                float tgh = tanhf(gg);
                float cold = is_init[b * T_ + t] ? 0.0f : cbuf[b * H_ + j];
                float cn = sf * cold + si * tgh;
                float hn = so * tanhf(cn);
                cbuf[b * H_ + j] = cn;

                float hr = __uint_as_float(tf32_bits(hn));
                float mnext = 1.0f;
                if (t + 1 < T_) mnext = is_init[b * T_ + t + 1] ? 0.0f : 1.0f;
                hm_w[b * H_ + j] = hr * mnext;
                if (LAYER == 0) h0u_w[b * H_ + j] = hr;
                if (t == T_ - 1) hf_w[b * H_ + j] = hn;
                if (LAYER == 1)
                    out[(size_t)b * T_ * H_ + (size_t)t * H_ + j] = hn;
            }
    }
}

// Wavefront-fused launch s: z=0 -> layer0(time s), z=1 -> layer1(time s-1).
__global__ void __launch_bounds__(256, 1) fused_step_kernel(
    const int* __restrict__ is_init,
    float* __restrict__ out,
    int s)
{
    extern __shared__ uint32_t smem[];
    if (blockIdx.z == 0) {
        if (s < T_) lstm_step_body<0>(smem, is_init, out, s);
    } else {
        if (s >= 1) lstm_step_body<1>(smem, is_init, out, s - 1);
    }
}

// ---------------- finalize ----------------
__global__ void finalize_kernel(float* __restrict__ out)
{
    const size_t off1 = (size_t)B_ * T_ * H_;
    const size_t off2 = off1 + (size_t)B_ * 2 * H_;
    int stride = gridDim.x * blockDim.x;
    for (int idx = blockIdx.x * blockDim.x + threadIdx.x; idx < B_ * H_; idx += stride) {
        int b = idx / H_, j = idx - b * H_;
        out[off1 + (size_t)b * 2 * H_ + j]      = g_h0f[idx];
        out[off1 + (size_t)b * 2 * H_ + H_ + j] = g_h1f[idx];
        out[off2 + (size_t)b * 2 * H_ + j]      = g_c0[idx];
        out[off2 + (size_t)b * 2 * H_ + H_ + j] = g_c1[idx];
    }
}

extern "C" void kernel_launch(void* const* d_in, const int* in_sizes, int n_in,
                              void* d_out, int out_size)
{
    const float* input   = (const float*)d_in[0];
    const int*   is_init = (const int*)d_in[1];
    const float* h       = (const float*)d_in[2];
    const float* c       = (const float*)d_in[3];
    const float* Wih0    = (const float*)d_in[4];
    const float* Whh0    = (const float*)d_in[5];
    const float* bih0    = (const float*)d_in[6];
    const float* bhh0    = (const float*)d_in[7];
    const float* Wih1    = (const float*)d_in[8];
    const float* Whh1    = (const float*)d_in[9];
    const float* bih1    = (const float*)d_in[10];
    const float* bhh1    = (const float*)d_in[11];
    float* out = (float*)d_out;

    static bool attr_set = false;
    if (!attr_set) {
        cudaFuncSetAttribute(fused_step_kernel,
                             cudaFuncAttributeMaxDynamicSharedMemorySize, SMEM_BYTES);
        attr_set = true;
    }

    permute_kernel<<<296, 256>>>(input, Wih0, Whh0, bih0, bhh0, Wih1, Whh1, bih1, bhh1);
    init_state_kernel<<<148, 256>>>(h, c, is_init);

    dim3 grid(G4 / BN, B_ / BM, 2);   // (16, 4, 2) = 128 blocks, single wave
    for (int s = 0; s <= T_; s++)
        fused_step_kernel<<<grid, 256, SMEM_BYTES>>>(is_init, out, s);

    finalize_kernel<<<148, 256>>>(out);
}

// round 9
// speedup vs baseline: 3.0137x; 1.0104x over previous
#include <cuda_runtime.h>
#include <math.h>
#include <stdint.h>

// Problem dims
#define B_  256
#define T_  128
#define I_  256
#define H_  512
#define G4  2048   // 4*H
#define K0  768    // I + H
#define K1  1024   // H + H

// GEMM tile: block 64(m) x 64(n), 8 warps (2m x 4n), warp 32x16, stage BK=32
#define BM  64
#define BN  64
#define BKK 32
#define SPK 36                       // k stride in smem (banks 4*gi+tg, conflict-free)
#define DEPTH 3                      // smem ring buffers (2 in flight)

#define A_WORDS (BM * SPK)           // 2304
#define B_WORDS (BN * SPK)           // 2304
#define SMEM_BYTES (DEPTH * (A_WORDS + B_WORDS) * 4)   // 55296 -> 2 blocks/SM

// ---------------- scratch ----------------
__device__ float g_W0p[(K0/8) * G4 * 8];   // [k/8][p][k%8], tf32-rounded
__device__ float g_W1p[(K1/8) * G4 * 8];
__device__ float g_b0p[G4];
__device__ float g_b1p[G4];
__device__ float g_x32[B_ * T_ * I_];      // tf32-rounded input
__device__ float g_h0 [2][B_ * H_];        // rounded, UNMASKED (layer1 input)
__device__ float g_h0m[2][B_ * H_];        // rounded, masked by next-step flag
__device__ float g_h1m[2][B_ * H_];
__device__ float g_c0[B_ * H_];
__device__ float g_c1[B_ * H_];
__device__ float g_h0f[B_ * H_];           // exact h(T-1) for h_n
__device__ float g_h1f[B_ * H_];

// column permutation: p -> original gate row q*H + j  (groups of 16 cols = 4 units)
__device__ __forceinline__ int p2norig(int p) {
    int g = p >> 4, pp = p & 15;
    int q = (pp < 8) ? (pp & 1) : (2 + (pp & 1));
    int u = (pp < 8) ? (pp >> 1) : ((pp - 8) >> 1);
    return q * H_ + g * 4 + u;
}

__device__ __forceinline__ uint32_t tf32_bits(float x) {
    uint32_t u;
    asm("cvt.rna.tf32.f32 %0, %1;" : "=r"(u) : "f"(x));
    return u;
}

__device__ __forceinline__ void cp16(uint32_t dst, const void* src) {
    asm volatile("cp.async.cg.shared.global [%0], [%1], 16;" :: "r"(dst), "l"(src));
}

// ---------------- prologue ----------------
__global__ void permute_kernel(const float* __restrict__ input,
                               const float* __restrict__ Wih0, const float* __restrict__ Whh0,
                               const float* __restrict__ bih0, const float* __restrict__ bhh0,
                               const float* __restrict__ Wih1, const float* __restrict__ Whh1,
                               const float* __restrict__ bih1, const float* __restrict__ bhh1)
{
    int stride = gridDim.x * blockDim.x;
    int tid0 = blockIdx.x * blockDim.x + threadIdx.x;

    for (int idx = tid0; idx < B_ * T_ * I_; idx += stride)
        g_x32[idx] = __uint_as_float(tf32_bits(input[idx]));

    for (int idx = tid0; idx < (K0/8) * G4 * 8; idx += stride) {
        int ki = idx & 7;
        int rest = idx >> 3;
        int p = rest & (G4 - 1);
        int kg = rest >> 11;
        int k = kg * 8 + ki;
        int norig = p2norig(p);
        float v = (k < I_) ? Wih0[norig * I_ + k] : Whh0[norig * H_ + (k - I_)];
        g_W0p[idx] = __uint_as_float(tf32_bits(v));
    }
    for (int idx = tid0; idx < (K1/8) * G4 * 8; idx += stride) {
        int ki = idx & 7;
        int rest = idx >> 3;
        int p = rest & (G4 - 1);
        int kg = rest >> 11;
        int k = kg * 8 + ki;
        int norig = p2norig(p);
        float v = (k < H_) ? Wih1[norig * H_ + k] : Whh1[norig * H_ + (k - H_)];
        g_W1p[idx] = __uint_as_float(tf32_bits(v));
    }
    for (int p = tid0; p < G4; p += stride) {
        int norig = p2norig(p);
        g_b0p[p] = bih0[norig] + bhh0[norig];
        g_b1p[p] = bih1[norig] + bhh1[norig];
    }
}

__global__ void init_state_kernel(const float* __restrict__ h, const float* __restrict__ c,
                                  const int* __restrict__ is_init)
{
    int stride = gridDim.x * blockDim.x;
    for (int idx = blockIdx.x * blockDim.x + threadIdx.x; idx < B_ * H_; idx += stride) {
        int b = idx / H_, j = idx - b * H_;
        float m0 = is_init[b * T_] ? 0.0f : 1.0f;
        g_h0m[0][idx] = __uint_as_float(tf32_bits(h[b * 2 * H_ + j])) * m0;
        g_h1m[0][idx] = __uint_as_float(tf32_bits(h[b * 2 * H_ + H_ + j])) * m0;
        g_c0[idx]     = c[b * 2 * H_ + j];
        g_c1[idx]     = c[b * 2 * H_ + H_ + j];
    }
}

// ---------------- fused tf32 mma GEMM + LSTM cell, cp.async 3-stage pipeline ----------------
template<int LAYER>
__device__ __forceinline__ void lstm_step_body(
    uint32_t* __restrict__ smem,
    const int* __restrict__ is_init,
    float* __restrict__ out,
    int t)
{
    constexpr int K = (LAYER == 0) ? K0 : K1;
    constexpr int NSTAGE = K / BKK;                 // 24 or 32
    const float* Wp = (LAYER == 0) ? g_W0p : g_W1p;
    const float* bp = (LAYER == 0) ? g_b0p : g_b1p;
    const int ping = t & 1;
    const float* hmsk = (LAYER == 0) ? g_h0m[ping] : g_h1m[ping];  // masked recurrence
    const float* h0u  = g_h0[ping ^ 1];                            // layer1 input (unmasked)
    float* cbuf = (LAYER == 0) ? g_c0 : g_c1;

    const int tid = threadIdx.x;
    const int bn = blockIdx.x;               // 0..31 (64 gate cols)
    const int bm = blockIdx.y;               // 0..3  (64 batch rows)
    const int wid = tid >> 5, lane = tid & 31;
    const int wm = wid >> 2;                 // 0..1
    const int wn = wid & 3;                  // 0..3
    const int gi = lane >> 2;                // 0..7
    const int tg = lane & 3;                 // 0..3

    uint32_t sbase = (uint32_t)__cvta_generic_to_shared(smem);
    uint32_t sA = sbase;
    uint32_t sB = sbase + DEPTH * A_WORDS * 4;
    const uint32_t* AsP = smem;                       // [buf][m][k] stride SPK
    const uint32_t* BsP = smem + DEPTH * A_WORDS;     // [buf][n][k] stride SPK

    auto issue = [&](int st, int buf) {
        const int k0 = st * BKK;
        const uint32_t aBuf = sA + buf * A_WORDS * 4;
        #pragma unroll
        for (int hh = 0; hh < 2; hh++) {
            int chunk = tid + 256 * hh;
            int m = chunk >> 3, kc = chunk & 7;
            int k = k0 + kc * 4;
            int gb = bm * BM + m;
            const float* src;
            if (LAYER == 0)
                src = (k < I_) ? (g_x32 + (size_t)gb * T_ * I_ + (size_t)t * I_ + k)
                               : (hmsk + gb * H_ + (k - I_));
            else
                src = (k < H_) ? (h0u + gb * H_ + k)
                               : (hmsk + gb * H_ + (k - H_));
            cp16(aBuf + (m * SPK + kc * 4) * 4, src);
        }
        const uint32_t bBuf = sB + buf * B_WORDS * 4;
        {
            int chunk = tid + 256;   // 512 chunks total, 2/thread
            int n0c = tid >> 3, kc0 = tid & 7;
            int n1c = chunk >> 3, kc1 = chunk & 7;
            int kg0 = (k0 >> 3) + (kc0 >> 1);
            int kg1 = (k0 >> 3) + (kc1 >> 1);
            const float* s0 = Wp + ((size_t)kg0 * G4 + bn * BN + n0c) * 8 + (kc0 & 1) * 4;
            const float* s1 = Wp + ((size_t)kg1 * G4 + bn * BN + n1c) * 8 + (kc1 & 1) * 4;
            cp16(bBuf + (n0c * SPK + kc0 * 4) * 4, s0);
            cp16(bBuf + (n1c * SPK + kc1 * 4) * 4, s1);
        }
    };

    float acc[2][2][4] = {};

    issue(0, 0); asm volatile("cp.async.commit_group;" ::: "memory");
    issue(1, 1); asm volatile("cp.async.commit_group;" ::: "memory");

    int buf = 0, nbuf = 2;
    #pragma unroll 4
    for (int st = 0; st < NSTAGE; st++) {
        asm volatile("cp.async.wait_group 1;" ::: "memory");
        __syncthreads();

        if (st + 2 < NSTAGE) issue(st + 2, nbuf);
        asm volatile("cp.async.commit_group;" ::: "memory");

        const uint32_t* Ab = AsP + buf * A_WORDS;
        const uint32_t* Bb = BsP + buf * B_WORDS;

        uint32_t a[2][2][4], b[2][2][2];
        auto ldfrag = [&](int kk, int pb) {
            #pragma unroll
            for (int mt = 0; mt < 2; mt++) {
                int m0 = wm * 32 + mt * 16 + gi;
                a[pb][mt][0] = Ab[m0 * SPK + kk + tg];
                a[pb][mt][1] = Ab[(m0 + 8) * SPK + kk + tg];
                a[pb][mt][2] = Ab[m0 * SPK + kk + tg + 4];
                a[pb][mt][3] = Ab[(m0 + 8) * SPK + kk + tg + 4];
            }
            #pragma unroll
            for (int nt = 0; nt < 2; nt++) {
                int n0 = wn * 16 + nt * 8 + gi;
                b[pb][nt][0] = Bb[n0 * SPK + kk + tg];
                b[pb][nt][1] = Bb[n0 * SPK + kk + tg + 4];
            }
        };

        ldfrag(0, 0);
        #pragma unroll
        for (int kq = 0; kq < 4; kq++) {
            if (kq < 3) ldfrag((kq + 1) * 8, (kq + 1) & 1);
            const int pb = kq & 1;
            #pragma unroll
            for (int mt = 0; mt < 2; mt++)
                #pragma unroll
                for (int nt = 0; nt < 2; nt++)
                    asm volatile(
                        "mma.sync.aligned.m16n8k8.row.col.f32.tf32.tf32.f32 "
                        "{%0,%1,%2,%3},{%4,%5,%6,%7},{%8,%9},{%0,%1,%2,%3};"
                        : "+f"(acc[mt][nt][0]), "+f"(acc[mt][nt][1]),
                          "+f"(acc[mt][nt][2]), "+f"(acc[mt][nt][3])
                        : "r"(a[pb][mt][0]), "r"(a[pb][mt][1]),
                          "r"(a[pb][mt][2]), "r"(a[pb][mt][3]),
                          "r"(b[pb][nt][0]), "r"(b[pb][nt][1]));
        }

        buf = (buf + 1 == DEPTH) ? 0 : buf + 1;
        nbuf = (nbuf + 1 == DEPTH) ? 0 : nbuf + 1;
    }

    // ---- fused LSTM cell epilogue ----
    float* h0u_w = g_h0[ping ^ 1];           // layer0 writes unmasked rounded h0(t)
    float* hm_w  = (LAYER == 0) ? g_h0m[ping ^ 1] : g_h1m[ping ^ 1];
    float* hf_w  = (LAYER == 0) ? g_h0f : g_h1f;

    const int g = bn * 4 + wn;               // group of 4 hidden units (16 cols)
    const int j = g * 4 + tg;
    const float bi = bp[g * 16 + 2 * tg];
    const float bf = bp[g * 16 + 2 * tg + 1];
    const float bg = bp[g * 16 + 8 + 2 * tg];
    const float bo = bp[g * 16 + 9 + 2 * tg];

    #pragma unroll
    for (int mt = 0; mt < 2; mt++)
        #pragma unroll
        for (int rr = 0; rr < 2; rr++) {
            int b = bm * BM + wm * 32 + mt * 16 + rr * 8 + gi;
            float ig = acc[mt][0][rr * 2 + 0] + bi;
            float fg = acc[mt][0][rr * 2 + 1] + bf;
            float gg = acc[mt][1][rr * 2 + 0] + bg;
            float og = acc[mt][1][rr * 2 + 1] + bo;
            float si = 1.0f / (1.0f + expf(-ig));
            float sf = 1.0f / (1.0f + expf(-fg));
            float so = 1.0f / (1.0f + expf(-og));
            float tgh = tanhf(gg);
            float cold = is_init[b * T_ + t] ? 0.0f : cbuf[b * H_ + j];
            float cn = sf * cold + si * tgh;
            float hn = so * tanhf(cn);
            cbuf[b * H_ + j] = cn;

            float hr = __uint_as_float(tf32_bits(hn));
            float mnext = 1.0f;
            if (t + 1 < T_) mnext = is_init[b * T_ + t + 1] ? 0.0f : 1.0f;
            hm_w[b * H_ + j] = hr * mnext;
            if (LAYER == 0) h0u_w[b * H_ + j] = hr;
            if (t == T_ - 1) hf_w[b * H_ + j] = hn;
            if (LAYER == 1)
                out[(size_t)b * T_ * H_ + (size_t)t * H_ + j] = hn;
        }
}

// Wavefront-fused launch s: z=0 -> layer0(time s), z=1 -> layer1(time s-1).
__global__ void __launch_bounds__(256, 2) fused_step_kernel(
    const int* __restrict__ is_init,
    float* __restrict__ out,
    int s)
{
    extern __shared__ uint32_t smem[];
    if (blockIdx.z == 0) {
        if (s < T_) lstm_step_body<0>(smem, is_init, out, s);
    } else {
        if (s >= 1) lstm_step_body<1>(smem, is_init, out, s - 1);
    }
}

// ---------------- finalize ----------------
__global__ void finalize_kernel(float* __restrict__ out)
{
    const size_t off1 = (size_t)B_ * T_ * H_;
    const size_t off2 = off1 + (size_t)B_ * 2 * H_;
    int stride = gridDim.x * blockDim.x;
    for (int idx = blockIdx.x * blockDim.x + threadIdx.x; idx < B_ * H_; idx += stride) {
        int b = idx / H_, j = idx - b * H_;
        out[off1 + (size_t)b * 2 * H_ + j]      = g_h0f[idx];
        out[off1 + (size_t)b * 2 * H_ + H_ + j] = g_h1f[idx];
        out[off2 + (size_t)b * 2 * H_ + j]      = g_c0[idx];
        out[off2 + (size_t)b * 2 * H_ + H_ + j] = g_c1[idx];
    }
}

extern "C" void kernel_launch(void* const* d_in, const int* in_sizes, int n_in,
                              void* d_out, int out_size)
{
    const float* input   = (const float*)d_in[0];
    const int*   is_init = (const int*)d_in[1];
    const float* h       = (const float*)d_in[2];
    const float* c       = (const float*)d_in[3];
    const float* Wih0    = (const float*)d_in[4];
    const float* Whh0    = (const float*)d_in[5];
    const float* bih0    = (const float*)d_in[6];
    const float* bhh0    = (const float*)d_in[7];
    const float* Wih1    = (const float*)d_in[8];
    const float* Whh1    = (const float*)d_in[9];
    const float* bih1    = (const float*)d_in[10];
    const float* bhh1    = (const float*)d_in[11];
    float* out = (float*)d_out;

    static bool attr_set = false;
    if (!attr_set) {
        cudaFuncSetAttribute(fused_step_kernel,
                             cudaFuncAttributeMaxDynamicSharedMemorySize, SMEM_BYTES);
        attr_set = true;
    }

    permute_kernel<<<296, 256>>>(input, Wih0, Whh0, bih0, bhh0, Wih1, Whh1, bih1, bhh1);
    init_state_kernel<<<148, 256>>>(h, c, is_init);

    dim3 grid(G4 / BN, B_ / BM, 2);   // (32, 4, 2) = 256 blocks, 2 blocks/SM
    for (int s = 0; s <= T_; s++)
        fused_step_kernel<<<grid, 256, SMEM_BYTES>>>(is_init, out, s);

    finalize_kernel<<<148, 256>>>(out);
}

// round 11
// speedup vs baseline: 4.4111x; 1.4637x over previous
#include <cuda_runtime.h>
#include <math.h>
#include <stdint.h>

// Problem dims
#define B_  256
#define T_  128
#define I_  256
#define H_  512
#define G4  2048   // 4*H
#define K0  768    // I + H
#define K1  1024   // H + H

// GEMM tile: block 64(m) x 64(n), 8 warps (2m x 4n), warp 32x16, stage BK=32
#define BM  64
#define BN  64
#define BKK 32
#define DEPTH 4

// smem: per stage, A[2][BM][16] + B[2][BN][16] words, k16-interleaved rows (64B)
#define A_ST (2 * BM * 16)            // 2048 words
#define B_ST (2 * BN * 16)            // 2048 words
#define STAGE_WORDS (A_ST + B_ST)     // 4096 words = 16KB
#define SMEM_BYTES (DEPTH * STAGE_WORDS * 4)   // 65536 -> 2 blocks/SM

// k16 interleave: position pos holds k = (pos>>2) + 4*(pos&3); pos(k) = 4*(k&3) + ((k>>2)&3)
__host__ __device__ __forceinline__ int kperm(int j) {      // value j -> position
    return (j & ~15) | (4 * (j & 3) + ((j >> 2) & 3));
}

// ---------------- scratch ----------------
__device__ float g_W0p[(K0/16) * G4 * 16];  // [k/16][p][16 pos], tf32, k-interleaved
__device__ float g_W1p[(K1/16) * G4 * 16];
__device__ float g_b0p[G4];
__device__ float g_b1p[G4];
__device__ float g_x32[B_ * T_ * I_];       // tf32-rounded, k-interleaved per 16
__device__ float g_h0 [2][B_ * H_];         // rounded, UNMASKED, j-interleaved
__device__ float g_h0m[2][B_ * H_];         // rounded, masked, j-interleaved
__device__ float g_h1m[2][B_ * H_];
__device__ float g_c0[B_ * H_];             // natural
__device__ float g_c1[B_ * H_];
__device__ float g_h0f[B_ * H_];            // exact h(T-1), natural
__device__ float g_h1f[B_ * H_];

// gate-column permutation: p -> original gate row q*H + j (groups of 16 cols = 4 units)
__device__ __forceinline__ int p2norig(int p) {
    int g = p >> 4, pp = p & 15;
    int q = (pp < 8) ? (pp & 1) : (2 + (pp & 1));
    int u = (pp < 8) ? (pp >> 1) : ((pp - 8) >> 1);
    return q * H_ + g * 4 + u;
}

__device__ __forceinline__ uint32_t tf32_bits(float x) {
    uint32_t u;
    asm("cvt.rna.tf32.f32 %0, %1;" : "=r"(u) : "f"(x));
    return u;
}

__device__ __forceinline__ void cp16(uint32_t dst, const void* src) {
    asm volatile("cp.async.cg.shared.global [%0], [%1], 16;" :: "r"(dst), "l"(src));
}

// ---------------- prologue ----------------
__global__ void permute_kernel(const float* __restrict__ input,
                               const float* __restrict__ Wih0, const float* __restrict__ Whh0,
                               const float* __restrict__ bih0, const float* __restrict__ bhh0,
                               const float* __restrict__ Wih1, const float* __restrict__ Whh1,
                               const float* __restrict__ bih1, const float* __restrict__ bhh1)
{
    int stride = gridDim.x * blockDim.x;
    int tid0 = blockIdx.x * blockDim.x + threadIdx.x;

    // x: tf32 round + k16 interleave (position pos <- source k = (pos>>2)+4*(pos&3))
    for (int idx = tid0; idx < B_ * T_ * I_; idx += stride) {
        int base = idx & ~15, pos = idx & 15;
        int ksrc = base + (pos >> 2) + 4 * (pos & 3);
        g_x32[idx] = __uint_as_float(tf32_bits(input[ksrc]));
    }
    // W0: [kb][p][pos]
    for (int idx = tid0; idx < (K0/16) * G4 * 16; idx += stride) {
        int pos = idx & 15;
        int p  = (idx >> 4) & (G4 - 1);
        int kb = idx >> 15;
        int k = kb * 16 + (pos >> 2) + 4 * (pos & 3);
        int norig = p2norig(p);
        float v = (k < I_) ? Wih0[norig * I_ + k] : Whh0[norig * H_ + (k - I_)];
        g_W0p[idx] = __uint_as_float(tf32_bits(v));
    }
    for (int idx = tid0; idx < (K1/16) * G4 * 16; idx += stride) {
        int pos = idx & 15;
        int p  = (idx >> 4) & (G4 - 1);
        int kb = idx >> 15;
        int k = kb * 16 + (pos >> 2) + 4 * (pos & 3);
        int norig = p2norig(p);
        float v = (k < H_) ? Wih1[norig * H_ + k] : Whh1[norig * H_ + (k - H_)];
        g_W1p[idx] = __uint_as_float(tf32_bits(v));
    }
    for (int p = tid0; p < G4; p += stride) {
        int norig = p2norig(p);
        g_b0p[p] = bih0[norig] + bhh0[norig];
        g_b1p[p] = bih1[norig] + bhh1[norig];
    }
}

__global__ void init_state_kernel(const float* __restrict__ h, const float* __restrict__ c,
                                  const int* __restrict__ is_init)
{
    int stride = gridDim.x * blockDim.x;
    for (int idx = blockIdx.x * blockDim.x + threadIdx.x; idx < B_ * H_; idx += stride) {
        int b = idx / H_, j = idx - b * H_;
        float m0 = is_init[b * T_] ? 0.0f : 1.0f;
        int jp = kperm(j);
        g_h0m[0][b * H_ + jp] = __uint_as_float(tf32_bits(h[b * 2 * H_ + j])) * m0;
        g_h1m[0][b * H_ + jp] = __uint_as_float(tf32_bits(h[b * 2 * H_ + H_ + j])) * m0;
        g_c0[idx] = c[b * 2 * H_ + j];
        g_c1[idx] = c[b * 2 * H_ + H_ + j];
    }
}

// ---------------- fused tf32 mma GEMM + LSTM cell, LDS.128 fragments ----------------
template<int LAYER>
__device__ __forceinline__ void lstm_step_body(
    uint32_t* __restrict__ smem,
    const int* __restrict__ is_init,
    float* __restrict__ out,
    int t)
{
    constexpr int K = (LAYER == 0) ? K0 : K1;
    constexpr int NSTAGE = K / BKK;                 // 24 or 32
    const float* Wp = (LAYER == 0) ? g_W0p : g_W1p;
    const float* bp = (LAYER == 0) ? g_b0p : g_b1p;
    const int ping = t & 1;
    const float* hmsk = (LAYER == 0) ? g_h0m[ping] : g_h1m[ping];  // masked, interleaved
    const float* h0u  = g_h0[ping ^ 1];                            // layer1 input
    float* cbuf = (LAYER == 0) ? g_c0 : g_c1;

    const int tid = threadIdx.x;
    const int bn = blockIdx.x;               // 0..31
    const int bm = blockIdx.y;               // 0..3
    const int wid = tid >> 5, lane = tid & 31;
    const int wm = wid >> 2;                 // 0..1
    const int wn = wid & 3;                  // 0..3
    const int gi = lane >> 2;                // 0..7
    const int tg = lane & 3;                 // 0..3

    const uint32_t sbase = (uint32_t)__cvta_generic_to_shared(smem);

    // producer: A 512 chunks (2/thread), B 512 chunks (2/thread); chunk = 16B
    // chunk c: qc = c&3, row = (c>>2)&63, ks16 = c>>8
    auto issue = [&](int st, int buf) {
        const int k0 = st * BKK;
        const uint32_t stB = sbase + buf * STAGE_WORDS * 4;
        #pragma unroll
        for (int hh = 0; hh < 2; hh++) {
            int c = tid + 256 * hh;
            int qc = c & 3, row = (c >> 2) & 63, ks16 = c >> 8;
            int base16 = k0 + ks16 * 16;
            int gb = bm * BM + row;
            const float* src;
            if (LAYER == 0)
                src = (base16 < I_)
                    ? (g_x32 + (size_t)gb * T_ * I_ + (size_t)t * I_ + base16 + qc * 4)
                    : (hmsk + (size_t)gb * H_ + (base16 - I_) + qc * 4);
            else
                src = (base16 < H_)
                    ? (h0u + (size_t)gb * H_ + base16 + qc * 4)
                    : (hmsk + (size_t)gb * H_ + (base16 - H_) + qc * 4);
            cp16(stB + (ks16 * BM * 16 + row * 16 + qc * 4) * 4, src);
        }
        #pragma unroll
        for (int hh = 0; hh < 2; hh++) {
            int c = tid + 256 * hh;
            int qc = c & 3, n = (c >> 2) & 63, ks16 = c >> 8;
            int kb = (k0 >> 4) + ks16;
            const float* src = Wp + ((size_t)kb * G4 + bn * BN + n) * 16 + qc * 4;
            cp16(stB + (A_ST + ks16 * BN * 16 + n * 16 + qc * 4) * 4, src);
        }
    };

    float acc[2][2][4] = {};

    issue(0, 0); asm volatile("cp.async.commit_group;" ::: "memory");
    issue(1, 1); asm volatile("cp.async.commit_group;" ::: "memory");
    issue(2, 2); asm volatile("cp.async.commit_group;" ::: "memory");

    int buf = 0, nbuf = 3;
    for (int st = 0; st < NSTAGE; st++) {
        asm volatile("cp.async.wait_group 2;" ::: "memory");
        __syncthreads();

        if (st + 3 < NSTAGE) issue(st + 3, nbuf);
        asm volatile("cp.async.commit_group;" ::: "memory");

        const uint32_t* Ab = smem + buf * STAGE_WORDS;
        const uint32_t* Bb = Ab + A_ST;

        #pragma unroll
        for (int ks16 = 0; ks16 < 2; ks16++) {
            // LDS.128 fragment loads: 16B holds k = {tg, tg+4, tg+8, tg+12}
            uint4 va[2][2], vb[2];
            #pragma unroll
            for (int mt = 0; mt < 2; mt++) {
                int m0 = wm * 32 + mt * 16 + gi;
                va[mt][0] = *(const uint4*)(Ab + ks16 * BM * 16 + m0 * 16 + tg * 4);
                va[mt][1] = *(const uint4*)(Ab + ks16 * BM * 16 + (m0 + 8) * 16 + tg * 4);
            }
            #pragma unroll
            for (int nt = 0; nt < 2; nt++) {
                int n0 = wn * 16 + nt * 8 + gi;
                vb[nt] = *(const uint4*)(Bb + ks16 * BN * 16 + n0 * 16 + tg * 4);
            }
            // k8 group 0: words .x (k=tg), .y (k=tg+4)
            #pragma unroll
            for (int mt = 0; mt < 2; mt++)
                #pragma unroll
                for (int nt = 0; nt < 2; nt++)
                    asm volatile(
                        "mma.sync.aligned.m16n8k8.row.col.f32.tf32.tf32.f32 "
                        "{%0,%1,%2,%3},{%4,%5,%6,%7},{%8,%9},{%0,%1,%2,%3};"
                        : "+f"(acc[mt][nt][0]), "+f"(acc[mt][nt][1]),
                          "+f"(acc[mt][nt][2]), "+f"(acc[mt][nt][3])
                        : "r"(va[mt][0].x), "r"(va[mt][1].x),
                          "r"(va[mt][0].y), "r"(va[mt][1].y),
                          "r"(vb[nt].x), "r"(vb[nt].y));
            // k8 group 1: words .z (k=tg+8), .w (k=tg+12)
            #pragma unroll
            for (int mt = 0; mt < 2; mt++)
                #pragma unroll
                for (int nt = 0; nt < 2; nt++)
                    asm volatile(
                        "mma.sync.aligned.m16n8k8.row.col.f32.tf32.tf32.f32 "
                        "{%0,%1,%2,%3},{%4,%5,%6,%7},{%8,%9},{%0,%1,%2,%3};"
                        : "+f"(acc[mt][nt][0]), "+f"(acc[mt][nt][1]),
                          "+f"(acc[mt][nt][2]), "+f"(acc[mt][nt][3])
                        : "r"(va[mt][0].z), "r"(va[mt][1].z),
                          "r"(va[mt][0].w), "r"(va[mt][1].w),
                          "r"(vb[nt].z), "r"(vb[nt].w));
        }

        buf = (buf + 1) & (DEPTH - 1);
        nbuf = (nbuf + 1) & (DEPTH - 1);
    }

    // ---- fused LSTM cell epilogue ----
    float* h0u_w = g_h0[ping ^ 1];
    float* hm_w  = (LAYER == 0) ? g_h0m[ping ^ 1] : g_h1m[ping ^ 1];
    float* hf_w  = (LAYER == 0) ? g_h0f : g_h1f;

    const int g = bn * 4 + wn;               // group of 4 hidden units (16 cols)
    const int j = g * 4 + tg;                // natural unit index
    const int jp = kperm(j);                 // interleaved position for h-state
    const float bi = bp[g * 16 + 2 * tg];
    const float bf = bp[g * 16 + 2 * tg + 1];
    const float bg = bp[g * 16 + 8 + 2 * tg];
    const float bo = bp[g * 16 + 9 + 2 * tg];

    #pragma unroll
    for (int mt = 0; mt < 2; mt++)
        #pragma unroll
        for (int rr = 0; rr < 2; rr++) {
            int b = bm * BM + wm * 32 + mt * 16 + rr * 8 + gi;
            float ig = acc[mt][0][rr * 2 + 0] + bi;
            float fg = acc[mt][0][rr * 2 + 1] + bf;
            float gg = acc[mt][1][rr * 2 + 0] + bg;
            float og = acc[mt][1][rr * 2 + 1] + bo;
            float si = 1.0f / (1.0f + expf(-ig));
            float sf = 1.0f / (1.0f + expf(-fg));
            float so = 1.0f / (1.0f + expf(-og));
            float tgh = tanhf(gg);
            float cold = is_init[b * T_ + t] ? 0.0f : cbuf[b * H_ + j];
            float cn = sf * cold + si * tgh;
            float hn = so * tanhf(cn);
            cbuf[b * H_ + j] = cn;

            float hr = __uint_as_float(tf32_bits(hn));
            float mnext = 1.0f;
            if (t + 1 < T_) mnext = is_init[b * T_ + t + 1] ? 0.0f : 1.0f;
            hm_w[b * H_ + jp] = hr * mnext;
            if (LAYER == 0) h0u_w[b * H_ + jp] = hr;
            if (t == T_ - 1) hf_w[b * H_ + j] = hn;
            if (LAYER == 1)
                out[(size_t)b * T_ * H_ + (size_t)t * H_ + j] = hn;
        }
}

// Wavefront-fused launch s: z=0 -> layer0(time s), z=1 -> layer1(time s-1).
__global__ void __launch_bounds__(256, 2) fused_step_kernel(
    const int* __restrict__ is_init,
    float* __restrict__ out,
    int s)
{
    extern __shared__ uint32_t smem[];
    if (blockIdx.z == 0) {
        if (s < T_) lstm_step_body<0>(smem, is_init, out, s);
    } else {
        if (s >= 1) lstm_step_body<1>(smem, is_init, out, s - 1);
    }
}

// ---------------- finalize ----------------
__global__ void finalize_kernel(float* __restrict__ out)
{
    const size_t off1 = (size_t)B_ * T_ * H_;
    const size_t off2 = off1 + (size_t)B_ * 2 * H_;
    int stride = gridDim.x * blockDim.x;
    for (int idx = blockIdx.x * blockDim.x + threadIdx.x; idx < B_ * H_; idx += stride) {
        int b = idx / H_, j = idx - b * H_;
        out[off1 + (size_t)b * 2 * H_ + j]      = g_h0f[idx];
        out[off1 + (size_t)b * 2 * H_ + H_ + j] = g_h1f[idx];
        out[off2 + (size_t)b * 2 * H_ + j]      = g_c0[idx];
        out[off2 + (size_t)b * 2 * H_ + H_ + j] = g_c1[idx];
    }
}

extern "C" void kernel_launch(void* const* d_in, const int* in_sizes, int n_in,
                              void* d_out, int out_size)
{
    const float* input   = (const float*)d_in[0];
    const int*   is_init = (const int*)d_in[1];
    const float* h       = (const float*)d_in[2];
    const float* c       = (const float*)d_in[3];
    const float* Wih0    = (const float*)d_in[4];
    const float* Whh0    = (const float*)d_in[5];
    const float* bih0    = (const float*)d_in[6];
    const float* bhh0    = (const float*)d_in[7];
    const float* Wih1    = (const float*)d_in[8];
    const float* Whh1    = (const float*)d_in[9];
    const float* bih1    = (const float*)d_in[10];
    const float* bhh1    = (const float*)d_in[11];
    float* out = (float*)d_out;

    static bool attr_set = false;
    if (!attr_set) {
        cudaFuncSetAttribute(fused_step_kernel,
                             cudaFuncAttributeMaxDynamicSharedMemorySize, SMEM_BYTES);
        attr_set = true;
    }

    permute_kernel<<<296, 256>>>(input, Wih0, Whh0, bih0, bhh0, Wih1, Whh1, bih1, bhh1);
    init_state_kernel<<<148, 256>>>(h, c, is_init);

    dim3 grid(G4 / BN, B_ / BM, 2);   // (32, 4, 2) = 256 blocks, 2 blocks/SM
    for (int s = 0; s <= T_; s++)
        fused_step_kernel<<<grid, 256, SMEM_BYTES>>>(is_init, out, s);

    finalize_kernel<<<148, 256>>>(out);
}